// round 4
// baseline (speedup 1.0000x reference)
#include <cuda_runtime.h>
#include <math.h>
#include <stdint.h>

#define NN   50000
#define NE   800000
#define NEL  850000
#define NG   64
#define FP   112
#define NF   110
#define MD   32
#define EH   128
#define NH   128
#define NIN  142
#define EFD  222

// -------- device scratch --------
__device__ float g_feats[NN * FP];
__device__ float g_P[(size_t)NN * 256];
__device__ float g_mi[NN * MD];
__device__ float g_hid[(size_t)NN * NH];
__device__ float g_sum[NG], g_sum2[NG];
__device__ float g_mean[NG], g_rstd[NG];
__device__ int   g_cnt[NN];
__device__ int   g_off[NN];
__device__ int4  g_edges[NEL];    // (src, dst, ea_bits, dist_bits), dst-sorted

__device__ __forceinline__ float silu_f(float x) {
    return x * (1.0f / (1.0f + __expf(-x)));
}
__device__ __forceinline__ uint32_t f2tf(float f) {
    uint32_t u; asm("cvt.rna.tf32.f32 %0, %1;" : "=r"(u) : "f"(f)); return u;
}
__device__ __forceinline__ void mma_tf32(float* d,
    uint32_t a0, uint32_t a1, uint32_t a2, uint32_t a3, uint32_t b0, uint32_t b1)
{
    asm volatile("mma.sync.aligned.m16n8k8.row.col.f32.tf32.tf32.f32 "
        "{%0,%1,%2,%3},{%4,%5,%6,%7},{%8,%9},{%0,%1,%2,%3};"
        : "+f"(d[0]), "+f"(d[1]), "+f"(d[2]), "+f"(d[3])
        : "r"(a0), "r"(a1), "r"(a2), "r"(a3), "r"(b0), "r"(b1));
}
__device__ __forceinline__ int lb_i(const int* __restrict__ a, int n, int v) {
    int lo = 0, hi = n;
    while (lo < hi) { int m = (lo + hi) >> 1; if (a[m] < v) lo = m + 1; else hi = m; }
    return lo;
}

// ==================== CSR build (once per launch; edge list static) ====================
__global__ void zeroc_kernel() {
    int i = blockIdx.x * blockDim.x + threadIdx.x;
    if (i < NN) g_cnt[i] = 0;
}
__global__ void hist_kernel(const int* __restrict__ ei) {
    int e = blockIdx.x * blockDim.x + threadIdx.x;
    if (e >= NEL) return;
    int d = (e < NE) ? ei[NE + e] : (e - NE);
    atomicAdd(&g_cnt[d], 1);
}
#define SCAN_PER 49   // 1024*49 = 50176 >= NN
__global__ void scan_kernel() {
    __shared__ int wsum[32];
    int t = threadIdx.x;
    int base = t * SCAN_PER;
    int s = 0;
    for (int i = 0; i < SCAN_PER; i++) {
        int idx = base + i;
        if (idx < NN) s += g_cnt[idx];
    }
    int lane = t & 31, wid = t >> 5;
    int v = s;
    #pragma unroll
    for (int o = 1; o < 32; o <<= 1) {
        int u = __shfl_up_sync(0xffffffffu, v, o);
        if (lane >= o) v += u;
    }
    if (lane == 31) wsum[wid] = v;
    __syncthreads();
    if (wid == 0) {
        int w = wsum[lane];
        #pragma unroll
        for (int o = 1; o < 32; o <<= 1) {
            int u = __shfl_up_sync(0xffffffffu, w, o);
            if (lane >= o) w += u;
        }
        wsum[lane] = w;
    }
    __syncthreads();
    int run = v - s + (wid ? wsum[wid - 1] : 0);
    for (int i = 0; i < SCAN_PER; i++) {
        int idx = base + i;
        if (idx < NN) { g_off[idx] = run; run += g_cnt[idx]; }
    }
}
__global__ void fill_kernel(const int* __restrict__ ei,
                            const float* __restrict__ eattr,
                            const float* __restrict__ pos)
{
    int e = blockIdx.x * blockDim.x + threadIdx.x;
    if (e >= NEL) return;
    int s, d; float a, dd;
    if (e < NE) {
        s = ei[e]; d = ei[NE + e];
        a = eattr[e];
        float dx = pos[s * 3 + 0] - pos[d * 3 + 0];
        float dy = pos[s * 3 + 1] - pos[d * 3 + 1];
        float dz = pos[s * 3 + 2] - pos[d * 3 + 2];
        dd = dx * dx + dy * dy + dz * dz;
    } else { s = d = e - NE; a = 0.f; dd = 0.f; }
    int p = atomicAdd(&g_off[d], 1);
    g_edges[p] = make_int4(s, d, __float_as_int(a), __float_as_int(dd));
}

// -------------------- embed (+ zero g_mi) --------------------
__global__ void embed_kernel(const float* __restrict__ x,
    const float* __restrict__ e0, const float* __restrict__ e1,
    const float* __restrict__ e2, const float* __restrict__ e3,
    const float* __restrict__ e4, const float* __restrict__ e5,
    const float* __restrict__ e6, const float* __restrict__ e7,
    const float* __restrict__ e8, const float* __restrict__ e9)
{
    long idx = (long)blockIdx.x * blockDim.x + threadIdx.x;
    if (idx < (long)NN * MD) g_mi[idx] = 0.f;
    if (idx >= (long)NN * FP) return;
    int n = (int)(idx / FP), k = (int)(idx % FP);
    float v = 0.f;
    if (k < 6) {
        int keep = (k == 0) ? 0 : (10 + k);
        v = x[n * 16 + keep];
    } else if (k < 38) {
        int code = (int)x[n * 16 + 1];
        v = e0[code * 32 + (k - 6)];
    } else if (k < 110) {
        int t = (k - 38) >> 3, c = (k - 38) & 7;
        int code = (int)x[n * 16 + 2 + t];
        const float* es[9] = {e1, e2, e3, e4, e5, e6, e7, e8, e9};
        v = es[t][code * 8 + c];
    }
    g_feats[idx] = v;
}

// ==================== precompP: [64x112] @ [112x128] per half, tf32 MMA ====================
#define PP_LDA 116
#define PP_LDB 136
#define PP_SMEM ((64 * PP_LDA + 112 * PP_LDB) * 4)
__global__ void precompP_kernel(const float* __restrict__ w1, int l)
{
    extern __shared__ float sm[];
    uint32_t* Xs = (uint32_t*)sm;
    uint32_t* Ws = Xs + 64 * PP_LDA;
    int tid = threadIdx.x;
    int m0 = blockIdx.x * 64;
    int half = blockIdx.y;

    if (blockIdx.x == 0 && half == 0 && tid < 2 * NG) {
        if (tid < NG) g_sum[tid] = 0.f; else g_sum2[tid - NG] = 0.f;
    }

    const float* wbase = w1 + (size_t)l * EFD * EH + (size_t)half * 110 * EH;
    for (int i = tid; i < 112 * PP_LDB; i += 256) {
        int k = i / PP_LDB, c = i % PP_LDB;
        Ws[i] = (k < 110 && c < 128) ? f2tf(wbase[(size_t)k * EH + c]) : 0u;
    }
    for (int i = tid; i < 64 * PP_LDA; i += 256) {
        int r = i / PP_LDA, c = i % PP_LDA;
        int n = m0 + r;
        Xs[i] = (n < NN && c < FP) ? f2tf(g_feats[(size_t)n * FP + c]) : 0u;
    }
    __syncthreads();

    int w = tid >> 5, lane = tid & 31;
    int g = lane >> 2, tig = lane & 3;
    int mp = w & 1;
    int ng = w >> 1;
    float acc[2][4][4];
    #pragma unroll
    for (int mi = 0; mi < 2; mi++)
        #pragma unroll
        for (int j = 0; j < 4; j++)
            #pragma unroll
            for (int q = 0; q < 4; q++) acc[mi][j][q] = 0.f;

    #pragma unroll 2
    for (int k0 = 0; k0 < 112; k0 += 8) {
        uint32_t a[2][4];
        #pragma unroll
        for (int mi = 0; mi < 2; mi++) {
            int r0 = mp * 32 + mi * 16;
            a[mi][0] = Xs[(r0 + g) * PP_LDA + k0 + tig];
            a[mi][1] = Xs[(r0 + g + 8) * PP_LDA + k0 + tig];
            a[mi][2] = Xs[(r0 + g) * PP_LDA + k0 + tig + 4];
            a[mi][3] = Xs[(r0 + g + 8) * PP_LDA + k0 + tig + 4];
        }
        uint32_t b[4][2];
        #pragma unroll
        for (int j = 0; j < 4; j++) {
            int c0 = ng * 32 + j * 8 + g;
            b[j][0] = Ws[(k0 + tig) * PP_LDB + c0];
            b[j][1] = Ws[(k0 + tig + 4) * PP_LDB + c0];
        }
        #pragma unroll
        for (int mi = 0; mi < 2; mi++)
            #pragma unroll
            for (int j = 0; j < 4; j++)
                mma_tf32(acc[mi][j], a[mi][0], a[mi][1], a[mi][2], a[mi][3], b[j][0], b[j][1]);
    }

    #pragma unroll
    for (int mi = 0; mi < 2; mi++) {
        int r = m0 + mp * 32 + mi * 16 + g;
        #pragma unroll
        for (int j = 0; j < 4; j++) {
            int col = half * 128 + ng * 32 + j * 8 + 2 * tig;
            if (r < NN)
                *(float2*)&g_P[(size_t)r * 256 + col] = make_float2(acc[mi][j][0], acc[mi][j][1]);
            if (r + 8 < NN)
                *(float2*)&g_P[(size_t)(r + 8) * 256 + col] = make_float2(acc[mi][j][2], acc[mi][j][3]);
        }
    }
}

// ==================== edge: sorted gather + tf32 MMA + run-compressed scatter ====================
#define E_LDA 132
#define E_LDB 40
#define E_LDM 36
#define EDGE_SMEM ((128 * E_LDA + 128 * E_LDB + 128 * 3 + 32 + 128 + 128 + 256) * 4)
__global__ void edge_kernel(
    const float* __restrict__ w1, const float* __restrict__ b1,
    const float* __restrict__ w2, const float* __restrict__ b2, int l)
{
    extern __shared__ float sm[];
    float* Hs   = sm;                       // 128 x 132 tf32 bits; reused as Ms 128 x 36
    float* W2s  = Hs + 128 * E_LDA;
    float* w220 = W2s + 128 * E_LDB;
    float* w221 = w220 + 128;
    float* b1s  = w221 + 128;
    float* b2s  = b1s + 128;
    float* ea0s = b2s + 32;
    float* dds  = ea0s + 128;
    int*   srcs = (int*)(dds + 128);
    int*   dsts = srcs + 128;
    uint32_t* HsU = (uint32_t*)Hs;
    uint32_t* WU  = (uint32_t*)W2s;
    float* Ms = Hs;

    int tid = threadIdx.x;
    int e0 = blockIdx.x * 128;
    const float* w1b = w1 + (size_t)l * EFD * EH;

    if (tid < 128) {
        w220[tid] = w1b[220 * EH + tid];
        w221[tid] = w1b[221 * EH + tid];
        b1s[tid]  = b1[l * EH + tid];
        int e = e0 + tid;
        int4 r = make_int4(-1, -1, 0, 0);
        if (e < NEL) r = g_edges[e];
        srcs[tid] = r.x; dsts[tid] = r.y;
        ea0s[tid] = __int_as_float(r.z); dds[tid] = __int_as_float(r.w);
    } else if (tid < 160) {
        b2s[tid - 128] = b2[l * MD + (tid - 128)];
    }
    for (int i = tid; i < 128 * 32; i += 256) {
        int k = i >> 5, c = i & 31;
        WU[k * E_LDB + c] = f2tf(w2[(size_t)l * EH * MD + i]);
    }
    __syncthreads();

    // phase 1: H = silu(Pd[dst] + Ps[src] + ea*w220 + dist*w221 + b1)
    #pragma unroll
    for (int it = 0; it < 16; ++it) {
        int idx = it * 256 + tid;
        int e = idx >> 5;
        int k0 = (idx & 31) * 4;
        int d = dsts[e];
        uint4 u = make_uint4(0u, 0u, 0u, 0u);
        if (d >= 0) {
            int s = srcs[e];
            float4 pd = *(const float4*)&g_P[(size_t)d * 256 + k0];
            float4 ps = *(const float4*)&g_P[(size_t)s * 256 + 128 + k0];
            float a = ea0s[e], dd = dds[e];
            u.x = f2tf(silu_f(pd.x + ps.x + a * w220[k0 + 0] + dd * w221[k0 + 0] + b1s[k0 + 0]));
            u.y = f2tf(silu_f(pd.y + ps.y + a * w220[k0 + 1] + dd * w221[k0 + 1] + b1s[k0 + 1]));
            u.z = f2tf(silu_f(pd.z + ps.z + a * w220[k0 + 2] + dd * w221[k0 + 2] + b1s[k0 + 2]));
            u.w = f2tf(silu_f(pd.w + ps.w + a * w220[k0 + 3] + dd * w221[k0 + 3] + b1s[k0 + 3]));
        }
        *(uint4*)&HsU[e * E_LDA + k0] = u;
    }
    __syncthreads();

    // phase 2: [128x128] @ [128x32] tf32 MMA
    int w = tid >> 5, lane = tid & 31;
    int g = lane >> 2, tig = lane & 3;
    int mp = w & 3;
    int np = w >> 2;
    float acc[2][2][4];
    #pragma unroll
    for (int mi = 0; mi < 2; mi++)
        #pragma unroll
        for (int ni = 0; ni < 2; ni++)
            #pragma unroll
            for (int q = 0; q < 4; q++) acc[mi][ni][q] = 0.f;

    #pragma unroll 2
    for (int k0 = 0; k0 < 128; k0 += 8) {
        uint32_t a[2][4];
        #pragma unroll
        for (int mi = 0; mi < 2; mi++) {
            int r0 = mp * 32 + mi * 16;
            a[mi][0] = HsU[(r0 + g) * E_LDA + k0 + tig];
            a[mi][1] = HsU[(r0 + g + 8) * E_LDA + k0 + tig];
            a[mi][2] = HsU[(r0 + g) * E_LDA + k0 + tig + 4];
            a[mi][3] = HsU[(r0 + g + 8) * E_LDA + k0 + tig + 4];
        }
        uint32_t b[2][2];
        #pragma unroll
        for (int ni = 0; ni < 2; ni++) {
            int c0 = np * 16 + ni * 8 + g;
            b[ni][0] = WU[(k0 + tig) * E_LDB + c0];
            b[ni][1] = WU[(k0 + tig + 4) * E_LDB + c0];
        }
        #pragma unroll
        for (int mi = 0; mi < 2; mi++)
            #pragma unroll
            for (int ni = 0; ni < 2; ni++)
                mma_tf32(acc[mi][ni], a[mi][0], a[mi][1], a[mi][2], a[mi][3], b[ni][0], b[ni][1]);
    }
    __syncthreads();

    #pragma unroll
    for (int mi = 0; mi < 2; mi++) {
        int r = mp * 32 + mi * 16 + g;
        #pragma unroll
        for (int ni = 0; ni < 2; ni++) {
            int c = np * 16 + ni * 8 + 2 * tig;
            Ms[r * E_LDM + c]           = silu_f(acc[mi][ni][0] + b2s[c]);
            Ms[r * E_LDM + c + 1]       = silu_f(acc[mi][ni][1] + b2s[c + 1]);
            Ms[(r + 8) * E_LDM + c]     = silu_f(acc[mi][ni][2] + b2s[c]);
            Ms[(r + 8) * E_LDM + c + 1] = silu_f(acc[mi][ni][3] + b2s[c + 1]);
        }
    }
    __syncthreads();

    // scatter: dst-sorted -> run leaders sum their run, one float4 RED per 4 cols
    int e = tid >> 1;
    int cb = (tid & 1) * 16;
    int d = dsts[e];
    if (d >= 0 && (e == 0 || dsts[e - 1] != d)) {
        float acc0[4] = {0, 0, 0, 0}, acc1[4] = {0, 0, 0, 0},
              acc2[4] = {0, 0, 0, 0}, acc3[4] = {0, 0, 0, 0};
        int j = e;
        do {
            const float4* mrow = (const float4*)&Ms[j * E_LDM + cb];
            float4 v0 = mrow[0], v1 = mrow[1], v2 = mrow[2], v3 = mrow[3];
            acc0[0] += v0.x; acc0[1] += v0.y; acc0[2] += v0.z; acc0[3] += v0.w;
            acc1[0] += v1.x; acc1[1] += v1.y; acc1[2] += v1.z; acc1[3] += v1.w;
            acc2[0] += v2.x; acc2[1] += v2.y; acc2[2] += v2.z; acc2[3] += v2.w;
            acc3[0] += v3.x; acc3[1] += v3.y; acc3[2] += v3.z; acc3[3] += v3.w;
            j++;
        } while (j < 128 && dsts[j] == d);
        float* dst = &g_mi[(size_t)d * MD + cb];
        atomicAdd((float4*)(dst + 0),  make_float4(acc0[0], acc0[1], acc0[2], acc0[3]));
        atomicAdd((float4*)(dst + 4),  make_float4(acc1[0], acc1[1], acc1[2], acc1[3]));
        atomicAdd((float4*)(dst + 8),  make_float4(acc2[0], acc2[1], acc2[2], acc2[3]));
        atomicAdd((float4*)(dst + 12), make_float4(acc3[0], acc3[1], acc3[2], acc3[3]));
    }
}

// -------------------- LN stats --------------------
__global__ void stats_partial_kernel(const int* __restrict__ batch)
{
    __shared__ int s_lo, s_hi;
    __shared__ float rs[8], rs2[8];
    int g = blockIdx.x, part = blockIdx.y;
    int tid = threadIdx.x;
    if (tid == 0) { s_lo = lb_i(batch, NN, g); s_hi = lb_i(batch, NN, g + 1); }
    __syncthreads();
    int total = (s_hi - s_lo) * FP;
    int chunk = (total + 7) >> 3;
    int st = part * chunk;
    int en = st + chunk; if (en > total) en = total;
    const float* base = g_feats + (size_t)s_lo * FP;
    float s = 0.f, s2 = 0.f;
    for (int i = st + tid; i < en; i += 256) { float v = base[i]; s += v; s2 += v * v; }
    #pragma unroll
    for (int o = 16; o; o >>= 1) {
        s  += __shfl_down_sync(0xffffffffu, s, o);
        s2 += __shfl_down_sync(0xffffffffu, s2, o);
    }
    if ((tid & 31) == 0) { rs[tid >> 5] = s; rs2[tid >> 5] = s2; }
    __syncthreads();
    if (tid == 0) {
        float a = 0.f, b = 0.f;
        for (int i = 0; i < 8; i++) { a += rs[i]; b += rs2[i]; }
        atomicAdd(&g_sum[g], a); atomicAdd(&g_sum2[g], b);
    }
}

__global__ void stats_final_kernel(const int* __restrict__ batch)
{
    int g = threadIdx.x;
    if (g >= NG) return;
    int lo = lb_i(batch, NN, g), hi = lb_i(batch, NN, g + 1);
    int c = hi - lo; if (c < 1) c = 1;
    float denom = (float)c * 110.f;
    float mean = g_sum[g] / denom;
    float var = g_sum2[g] / denom - mean * mean;
    var = fmaxf(var, 0.f);
    g_mean[g] = mean;
    g_rstd[g] = rsqrtf(var + 1e-5f);
}

// ==================== node1: [64x144] @ [144x64] per half, tf32 MMA ====================
#define N1_LDA 148
#define N1_LDB 72
#define N1_SMEM ((64 * N1_LDA + 144 * N1_LDB) * 4)
__global__ void node1_kernel(const int* __restrict__ batch,
    const float* __restrict__ nw1, const float* __restrict__ nb1,
    const float* __restrict__ lnw, const float* __restrict__ lnb, int l)
{
    extern __shared__ float sm[];
    uint32_t* Xs = (uint32_t*)sm;
    uint32_t* Ws = Xs + 64 * N1_LDA;
    int tid = threadIdx.x;
    int m0 = blockIdx.x * 64;
    int half = blockIdx.y;

    const float* w1b = nw1 + (size_t)l * NIN * NH;
    for (int i = tid; i < 144 * N1_LDB; i += 256) {
        int k = i / N1_LDB, c = i % N1_LDB;
        Ws[i] = (k < NIN && c < 64) ? f2tf(w1b[(size_t)k * NH + half * 64 + c]) : 0u;
    }
    for (int i = tid; i < 64 * N1_LDA; i += 256) {
        int n = m0 + i / N1_LDA, k = i % N1_LDA;
        float v = 0.f;
        if (n < NN) {
            if (k < NF) {
                int gg = batch[n];
                float f = g_feats[(size_t)n * FP + k];
                v = lnw[l * NF + k] * ((f - g_mean[gg]) * g_rstd[gg]) + lnb[l * NF + k];
            } else if (k < NIN) {
                v = g_mi[(size_t)n * MD + (k - NF)];
            }
        }
        Xs[i] = f2tf(v);
    }
    __syncthreads();

    int w = tid >> 5, lane = tid & 31;
    int g = lane >> 2, tig = lane & 3;
    int mp = w & 1;
    int np = w >> 1;
    float acc[2][2][4];
    #pragma unroll
    for (int mi = 0; mi < 2; mi++)
        #pragma unroll
        for (int ni = 0; ni < 2; ni++)
            #pragma unroll
            for (int q = 0; q < 4; q++) acc[mi][ni][q] = 0.f;

    #pragma unroll 2
    for (int k0 = 0; k0 < 144; k0 += 8) {
        uint32_t a[2][4];
        #pragma unroll
        for (int mi = 0; mi < 2; mi++) {
            int r0 = mp * 32 + mi * 16;
            a[mi][0] = Xs[(r0 + g) * N1_LDA + k0 + tig];
            a[mi][1] = Xs[(r0 + g + 8) * N1_LDA + k0 + tig];
            a[mi][2] = Xs[(r0 + g) * N1_LDA + k0 + tig + 4];
            a[mi][3] = Xs[(r0 + g + 8) * N1_LDA + k0 + tig + 4];
        }
        uint32_t b[2][2];
        #pragma unroll
        for (int ni = 0; ni < 2; ni++) {
            int c0 = np * 16 + ni * 8 + g;
            b[ni][0] = Ws[(k0 + tig) * N1_LDB + c0];
            b[ni][1] = Ws[(k0 + tig + 4) * N1_LDB + c0];
        }
        #pragma unroll
        for (int mi = 0; mi < 2; mi++)
            #pragma unroll
            for (int ni = 0; ni < 2; ni++)
                mma_tf32(acc[mi][ni], a[mi][0], a[mi][1], a[mi][2], a[mi][3], b[ni][0], b[ni][1]);
    }

    #pragma unroll
    for (int mi = 0; mi < 2; mi++) {
        int r = m0 + mp * 32 + mi * 16 + g;
        #pragma unroll
        for (int ni = 0; ni < 2; ni++) {
            int cg = half * 64 + np * 16 + ni * 8 + 2 * tig;
            float bb0 = nb1[l * NH + cg], bb1 = nb1[l * NH + cg + 1];
            if (r < NN)
                *(float2*)&g_hid[(size_t)r * NH + cg] =
                    make_float2(silu_f(acc[mi][ni][0] + bb0), silu_f(acc[mi][ni][1] + bb1));
            if (r + 8 < NN)
                *(float2*)&g_hid[(size_t)(r + 8) * NH + cg] =
                    make_float2(silu_f(acc[mi][ni][2] + bb0), silu_f(acc[mi][ni][3] + bb1));
        }
    }
}

// ==================== node2: feats += hid @ W2 + b2, tf32 MMA ; zero g_mi ====================
#define N2_LDA 132
#define N2_LDB 120
#define N2_SMEM ((64 * N2_LDA + 128 * N2_LDB) * 4)
__global__ void node2_kernel(const float* __restrict__ nw2, const float* __restrict__ nb2, int l)
{
    extern __shared__ float sm[];
    uint32_t* Xs = (uint32_t*)sm;              // 64 x 132 (hid tf32)
    uint32_t* Ws = Xs + 64 * N2_LDA;           // 128 x 120 (cols >=110 zero)
    int tid = threadIdx.x;
    int m0 = blockIdx.x * 64;

    const float* w2b = nw2 + (size_t)l * NH * NF;
    for (int i = tid; i < 128 * N2_LDB; i += 256) {
        int k = i / N2_LDB, c = i % N2_LDB;
        Ws[i] = (c < NF) ? f2tf(w2b[(size_t)k * NF + c]) : 0u;
    }
    for (int i = tid; i < 64 * N2_LDA; i += 256) {
        int r = i / N2_LDA, c = i % N2_LDA;
        int n = m0 + r;
        Xs[i] = (n < NN && c < NH) ? f2tf(g_hid[(size_t)n * NH + c]) : 0u;
    }
    __syncthreads();

    int w = tid >> 5, lane = tid & 31;
    int g = lane >> 2, tig = lane & 3;
    int mp = w & 3;          // rows mp*16 .. +15
    int np = w >> 2;         // cols np*56 .. +55 (7 x 8)
    float acc[7][4];
    #pragma unroll
    for (int j = 0; j < 7; j++)
        #pragma unroll
        for (int q = 0; q < 4; q++) acc[j][q] = 0.f;

    #pragma unroll 2
    for (int k0 = 0; k0 < 128; k0 += 8) {
        uint32_t a0 = Xs[(mp * 16 + g) * N2_LDA + k0 + tig];
        uint32_t a1 = Xs[(mp * 16 + g + 8) * N2_LDA + k0 + tig];
        uint32_t a2 = Xs[(mp * 16 + g) * N2_LDA + k0 + tig + 4];
        uint32_t a3 = Xs[(mp * 16 + g + 8) * N2_LDA + k0 + tig + 4];
        uint32_t b[7][2];
        #pragma unroll
        for (int j = 0; j < 7; j++) {
            int c0 = np * 56 + j * 8 + g;
            b[j][0] = Ws[(k0 + tig) * N2_LDB + c0];
            b[j][1] = Ws[(k0 + tig + 4) * N2_LDB + c0];
        }
        #pragma unroll
        for (int j = 0; j < 7; j++)
            mma_tf32(acc[j], a0, a1, a2, a3, b[j][0], b[j][1]);
    }

    #pragma unroll
    for (int j = 0; j < 7; j++) {
        int c = np * 56 + j * 8 + 2 * tig;
        if (c >= NF) continue;                   // c=110 pad columns
        float bb0 = nb2[l * NF + c], bb1 = nb2[l * NF + c + 1];
        int r = m0 + mp * 16 + g;
        if (r < NN) {
            float2 f = *(float2*)&g_feats[(size_t)r * FP + c];
            f.x += acc[j][0] + bb0; f.y += acc[j][1] + bb1;
            *(float2*)&g_feats[(size_t)r * FP + c] = f;
        }
        if (r + 8 < NN) {
            float2 f = *(float2*)&g_feats[(size_t)(r + 8) * FP + c];
            f.x += acc[j][2] + bb0; f.y += acc[j][3] + bb1;
            *(float2*)&g_feats[(size_t)(r + 8) * FP + c] = f;
        }
    }
    __syncthreads();
    for (int i = tid; i < 64 * MD; i += 256) {
        int n = m0 + i / MD;
        if (n < NN) g_mi[(size_t)n * MD + (i % MD)] = 0.f;
    }
}

// -------------------- global mean pool --------------------
__global__ void pool_kernel(const int* __restrict__ batch, float* __restrict__ out)
{
    __shared__ int s_lo, s_hi;
    __shared__ float red[256];
    int g = blockIdx.x, tid = threadIdx.x;
    if (tid == 0) { s_lo = lb_i(batch, NN, g); s_hi = lb_i(batch, NN, g + 1); }
    __syncthreads();
    float s = 0.f;
    if (tid < 2 * FP) {
        int part = tid / FP;
        int k = tid % FP;
        for (int n = s_lo + part; n < s_hi; n += 2)
            s += g_feats[(size_t)n * FP + k];
    }
    red[tid] = s;
    __syncthreads();
    if (tid < NF) {
        int c = s_hi - s_lo; if (c < 1) c = 1;
        out[g * NF + tid] = (red[tid] + red[tid + FP]) / (float)c;
    }
}

// -------------------- launch --------------------
extern "C" void kernel_launch(void* const* d_in, const int* in_sizes, int n_in,
                              void* d_out, int out_size)
{
    const float* x     = (const float*)d_in[0];
    const int*   ei    = (const int*)  d_in[1];
    const float* eattr = (const float*)d_in[2];
    const float* pos   = (const float*)d_in[3];
    const int*   batch = (const int*)  d_in[4];
    const float* emb[10];
    for (int i = 0; i < 10; i++) emb[i] = (const float*)d_in[5 + i];
    const float* ew1 = (const float*)d_in[15];
    const float* eb1 = (const float*)d_in[16];
    const float* ew2 = (const float*)d_in[17];
    const float* eb2 = (const float*)d_in[18];
    const float* nw1 = (const float*)d_in[19];
    const float* nb1 = (const float*)d_in[20];
    const float* nw2 = (const float*)d_in[21];
    const float* nb2 = (const float*)d_in[22];
    const float* lnw = (const float*)d_in[23];
    const float* lnb = (const float*)d_in[24];
    float* out = (float*)d_out;

    cudaFuncSetAttribute(precompP_kernel, cudaFuncAttributeMaxDynamicSharedMemorySize, PP_SMEM);
    cudaFuncSetAttribute(edge_kernel,     cudaFuncAttributeMaxDynamicSharedMemorySize, EDGE_SMEM);
    cudaFuncSetAttribute(node1_kernel,    cudaFuncAttributeMaxDynamicSharedMemorySize, N1_SMEM);
    cudaFuncSetAttribute(node2_kernel,    cudaFuncAttributeMaxDynamicSharedMemorySize, N2_SMEM);

    // CSR build (edge list static across layers)
    zeroc_kernel<<<(NN + 255) / 256, 256>>>();
    hist_kernel<<<(NEL + 255) / 256, 256>>>(ei);
    scan_kernel<<<1, 1024>>>();
    fill_kernel<<<(NEL + 255) / 256, 256>>>(ei, eattr, pos);

    embed_kernel<<<(NN * FP + 255) / 256, 256>>>(x, emb[0], emb[1], emb[2], emb[3],
                                                 emb[4], emb[5], emb[6], emb[7], emb[8], emb[9]);

    for (int l = 0; l < 2; l++) {
        precompP_kernel<<<dim3((NN + 63) / 64, 2), 256, PP_SMEM>>>(ew1, l);
        stats_partial_kernel<<<dim3(NG, 8), 256>>>(batch);
        stats_final_kernel<<<1, 64>>>(batch);
        edge_kernel<<<(NEL + 127) / 128, 256, EDGE_SMEM>>>(ew1, eb1, ew2, eb2, l);
        node1_kernel<<<dim3((NN + 63) / 64, 2), 256, N1_SMEM>>>(batch, nw1, nb1, lnw, lnb, l);
        node2_kernel<<<(NN + 63) / 64, 256, N2_SMEM>>>(nw2, nb2, l);
    }
    pool_kernel<<<NG, 256>>>(batch, out);
}

// round 6
// speedup vs baseline: 1.2374x; 1.2374x over previous
#include <cuda_runtime.h>
#include <math.h>
#include <stdint.h>

#define NN   50000
#define NE   800000
#define NEL  850000
#define NG   64
#define FP   112
#define NF   110
#define MD   32
#define EH   128
#define NH   128
#define NIN  142
#define EFD  222

// -------- device scratch --------
__device__ float g_feats[NN * FP];
__device__ float g_P[(size_t)NN * 256];
__device__ float g_mi[NN * MD];
__device__ float g_ea[NE * 2];
__device__ float g_sum[NG], g_sum2[NG];
__device__ float g_mean[NG], g_rstd[NG];

__device__ __forceinline__ float silu_f(float x) {
    return x * (1.0f / (1.0f + __expf(-x)));
}
__device__ __forceinline__ uint32_t f2tf(float f) {
    uint32_t u; asm("cvt.rna.tf32.f32 %0, %1;" : "=r"(u) : "f"(f)); return u;
}
__device__ __forceinline__ void mma_tf32(float* d,
    uint32_t a0, uint32_t a1, uint32_t a2, uint32_t a3, uint32_t b0, uint32_t b1)
{
    asm volatile("mma.sync.aligned.m16n8k8.row.col.f32.tf32.tf32.f32 "
        "{%0,%1,%2,%3},{%4,%5,%6,%7},{%8,%9},{%0,%1,%2,%3};"
        : "+f"(d[0]), "+f"(d[1]), "+f"(d[2]), "+f"(d[3])
        : "r"(a0), "r"(a1), "r"(a2), "r"(a3), "r"(b0), "r"(b1));
}
__device__ __forceinline__ int lb_i(const int* __restrict__ a, int n, int v) {
    int lo = 0, hi = n;
    while (lo < hi) { int m = (lo + hi) >> 1; if (a[m] < v) lo = m + 1; else hi = m; }
    return lo;
}

// -------------------- embed (+ zero g_mi) --------------------
__global__ void embed_kernel(const float* __restrict__ x,
    const float* __restrict__ e0, const float* __restrict__ e1,
    const float* __restrict__ e2, const float* __restrict__ e3,
    const float* __restrict__ e4, const float* __restrict__ e5,
    const float* __restrict__ e6, const float* __restrict__ e7,
    const float* __restrict__ e8, const float* __restrict__ e9)
{
    long idx = (long)blockIdx.x * blockDim.x + threadIdx.x;
    if (idx < (long)NN * MD) g_mi[idx] = 0.f;
    if (idx >= (long)NN * FP) return;
    int n = (int)(idx / FP), k = (int)(idx % FP);
    float v = 0.f;
    if (k < 6) {
        int keep = (k == 0) ? 0 : (10 + k);
        v = x[n * 16 + keep];
    } else if (k < 38) {
        int code = (int)x[n * 16 + 1];
        v = e0[code * 32 + (k - 6)];
    } else if (k < 110) {
        int t = (k - 38) >> 3, c = (k - 38) & 7;
        int code = (int)x[n * 16 + 2 + t];
        const float* es[9] = {e1, e2, e3, e4, e5, e6, e7, e8, e9};
        v = es[t][code * 8 + c];
    }
    g_feats[idx] = v;
}

// -------------------- edge attr + rel dist --------------------
__global__ void ea_kernel(const int* __restrict__ ei,
                          const float* __restrict__ eattr,
                          const float* __restrict__ pos)
{
    int e = blockIdx.x * blockDim.x + threadIdx.x;
    if (e >= NE) return;
    int s = ei[e], d = ei[NE + e];
    float dx = pos[s * 3 + 0] - pos[d * 3 + 0];
    float dy = pos[s * 3 + 1] - pos[d * 3 + 1];
    float dz = pos[s * 3 + 2] - pos[d * 3 + 2];
    g_ea[2 * e + 0] = eattr[e];
    g_ea[2 * e + 1] = dx * dx + dy * dy + dz * dz;
}

// ==================== precompP: [64x112] @ [112x128] per half, tf32 MMA ====================
#define PP_LDA 116
#define PP_LDB 136
#define PP_SMEM ((64 * PP_LDA + 112 * PP_LDB) * 4)
__global__ void precompP_kernel(const float* __restrict__ w1, int l)
{
    extern __shared__ float sm[];
    uint32_t* Xs = (uint32_t*)sm;
    uint32_t* Ws = Xs + 64 * PP_LDA;
    int tid = threadIdx.x;
    int m0 = blockIdx.x * 64;
    int half = blockIdx.y;

    if (blockIdx.x == 0 && half == 0 && tid < 2 * NG) {
        if (tid < NG) g_sum[tid] = 0.f; else g_sum2[tid - NG] = 0.f;
    }

    const float* wbase = w1 + (size_t)l * EFD * EH + (size_t)half * 110 * EH;
    for (int i = tid; i < 112 * PP_LDB; i += 256) {
        int k = i / PP_LDB, c = i % PP_LDB;
        Ws[i] = (k < 110 && c < 128) ? f2tf(wbase[(size_t)k * EH + c]) : 0u;
    }
    for (int i = tid; i < 64 * PP_LDA; i += 256) {
        int r = i / PP_LDA, c = i % PP_LDA;
        int n = m0 + r;
        Xs[i] = (n < NN && c < FP) ? f2tf(g_feats[(size_t)n * FP + c]) : 0u;
    }
    __syncthreads();

    int w = tid >> 5, lane = tid & 31;
    int g = lane >> 2, tig = lane & 3;
    int mp = w & 1;
    int ng = w >> 1;
    float acc[2][4][4];
    #pragma unroll
    for (int mi = 0; mi < 2; mi++)
        #pragma unroll
        for (int j = 0; j < 4; j++)
            #pragma unroll
            for (int q = 0; q < 4; q++) acc[mi][j][q] = 0.f;

    #pragma unroll 2
    for (int k0 = 0; k0 < 112; k0 += 8) {
        uint32_t a[2][4];
        #pragma unroll
        for (int mi = 0; mi < 2; mi++) {
            int r0 = mp * 32 + mi * 16;
            a[mi][0] = Xs[(r0 + g) * PP_LDA + k0 + tig];
            a[mi][1] = Xs[(r0 + g + 8) * PP_LDA + k0 + tig];
            a[mi][2] = Xs[(r0 + g) * PP_LDA + k0 + tig + 4];
            a[mi][3] = Xs[(r0 + g + 8) * PP_LDA + k0 + tig + 4];
        }
        uint32_t b[4][2];
        #pragma unroll
        for (int j = 0; j < 4; j++) {
            int c0 = ng * 32 + j * 8 + g;
            b[j][0] = Ws[(k0 + tig) * PP_LDB + c0];
            b[j][1] = Ws[(k0 + tig + 4) * PP_LDB + c0];
        }
        #pragma unroll
        for (int mi = 0; mi < 2; mi++)
            #pragma unroll
            for (int j = 0; j < 4; j++)
                mma_tf32(acc[mi][j], a[mi][0], a[mi][1], a[mi][2], a[mi][3], b[j][0], b[j][1]);
    }

    #pragma unroll
    for (int mi = 0; mi < 2; mi++) {
        int r = m0 + mp * 32 + mi * 16 + g;
        #pragma unroll
        for (int j = 0; j < 4; j++) {
            int col = half * 128 + ng * 32 + j * 8 + 2 * tig;
            if (r < NN)
                *(float2*)&g_P[(size_t)r * 256 + col] = make_float2(acc[mi][j][0], acc[mi][j][1]);
            if (r + 8 < NN)
                *(float2*)&g_P[(size_t)(r + 8) * 256 + col] = make_float2(acc[mi][j][2], acc[mi][j][3]);
        }
    }
}

// ==================== persistent edge: gather + tf32 MMA + scatter ====================
#define E_LDA 132
#define E_LDB 40
#define E_LDM 36
#define E_NT  ((NEL + 127) / 128)
#define E_GRID 296
#define EDGE_SMEM ((128 * E_LDA + 128 * E_LDB + 128 * 3 + 32 + 128 + 128 + 256) * 4)
__global__ void edge_kernel(const int* __restrict__ ei,
    const float* __restrict__ w1, const float* __restrict__ b1,
    const float* __restrict__ w2, const float* __restrict__ b2, int l)
{
    extern __shared__ float sm[];
    float* Hs   = sm;                       // 128 x 132 tf32 bits; reused as Ms 128 x 36
    float* W2s  = Hs + 128 * E_LDA;
    float* w220 = W2s + 128 * E_LDB;
    float* w221 = w220 + 128;
    float* b1s  = w221 + 128;
    float* b2s  = b1s + 128;
    float* ea0s = b2s + 32;
    float* dds  = ea0s + 128;
    int*   srcs = (int*)(dds + 128);
    int*   dsts = srcs + 128;
    uint32_t* HsU = (uint32_t*)Hs;
    uint32_t* WU  = (uint32_t*)W2s;
    float* Ms = Hs;

    int tid = threadIdx.x;
    const float* w1b = w1 + (size_t)l * EFD * EH;

    // weights resident for whole kernel
    if (tid < 128) {
        w220[tid] = w1b[220 * EH + tid];
        w221[tid] = w1b[221 * EH + tid];
        b1s[tid]  = b1[l * EH + tid];
    } else if (tid < 160) {
        b2s[tid - 128] = b2[l * MD + (tid - 128)];
    }
    for (int i = tid; i < 128 * 32; i += 256) {
        int k = i >> 5, c = i & 31;
        WU[k * E_LDB + c] = f2tf(w2[(size_t)l * EH * MD + i]);
    }

    int w = tid >> 5, lane = tid & 31;
    int g = lane >> 2, tig = lane & 3;
    int mp = w & 3;
    int np = w >> 2;

    for (int tile = blockIdx.x; tile < E_NT; tile += E_GRID) {
        int e0 = tile * 128;
        __syncthreads();    // smem safe to overwrite (also covers first-iter W load)
        if (tid < 128) {
            int e = e0 + tid;
            int s = -1, d = -1; float a = 0.f, dd = 0.f;
            if (e < NEL) {
                if (e < NE) { s = ei[e]; d = ei[NE + e]; a = g_ea[2 * e]; dd = g_ea[2 * e + 1]; }
                else        { s = d = e - NE; }
            }
            srcs[tid] = s; dsts[tid] = d; ea0s[tid] = a; dds[tid] = dd;
        }
        __syncthreads();

        // phase 1: H = silu(Pd[dst] + Ps[src] + ea*w220 + dist*w221 + b1)
        #pragma unroll
        for (int it = 0; it < 16; ++it) {
            int idx = it * 256 + tid;
            int e = idx >> 5;
            int k0 = (idx & 31) * 4;
            int d = dsts[e];
            uint4 u = make_uint4(0u, 0u, 0u, 0u);
            if (d >= 0) {
                int s = srcs[e];
                float4 pd = *(const float4*)&g_P[(size_t)d * 256 + k0];
                float4 ps = *(const float4*)&g_P[(size_t)s * 256 + 128 + k0];
                float a = ea0s[e], dd = dds[e];
                u.x = f2tf(silu_f(pd.x + ps.x + a * w220[k0 + 0] + dd * w221[k0 + 0] + b1s[k0 + 0]));
                u.y = f2tf(silu_f(pd.y + ps.y + a * w220[k0 + 1] + dd * w221[k0 + 1] + b1s[k0 + 1]));
                u.z = f2tf(silu_f(pd.z + ps.z + a * w220[k0 + 2] + dd * w221[k0 + 2] + b1s[k0 + 2]));
                u.w = f2tf(silu_f(pd.w + ps.w + a * w220[k0 + 3] + dd * w221[k0 + 3] + b1s[k0 + 3]));
            }
            *(uint4*)&HsU[e * E_LDA + k0] = u;
        }
        __syncthreads();

        // phase 2: [128x128] @ [128x32] tf32 MMA
        float acc[2][2][4];
        #pragma unroll
        for (int mi = 0; mi < 2; mi++)
            #pragma unroll
            for (int ni = 0; ni < 2; ni++)
                #pragma unroll
                for (int q = 0; q < 4; q++) acc[mi][ni][q] = 0.f;

        #pragma unroll 2
        for (int k0 = 0; k0 < 128; k0 += 8) {
            uint32_t a[2][4];
            #pragma unroll
            for (int mi = 0; mi < 2; mi++) {
                int r0 = mp * 32 + mi * 16;
                a[mi][0] = HsU[(r0 + g) * E_LDA + k0 + tig];
                a[mi][1] = HsU[(r0 + g + 8) * E_LDA + k0 + tig];
                a[mi][2] = HsU[(r0 + g) * E_LDA + k0 + tig + 4];
                a[mi][3] = HsU[(r0 + g + 8) * E_LDA + k0 + tig + 4];
            }
            uint32_t b[2][2];
            #pragma unroll
            for (int ni = 0; ni < 2; ni++) {
                int c0 = np * 16 + ni * 8 + g;
                b[ni][0] = WU[(k0 + tig) * E_LDB + c0];
                b[ni][1] = WU[(k0 + tig + 4) * E_LDB + c0];
            }
            #pragma unroll
            for (int mi = 0; mi < 2; mi++)
                #pragma unroll
                for (int ni = 0; ni < 2; ni++)
                    mma_tf32(acc[mi][ni], a[mi][0], a[mi][1], a[mi][2], a[mi][3], b[ni][0], b[ni][1]);
        }
        __syncthreads();   // done reading Hs; reuse as Ms

        #pragma unroll
        for (int mi = 0; mi < 2; mi++) {
            int r = mp * 32 + mi * 16 + g;
            #pragma unroll
            for (int ni = 0; ni < 2; ni++) {
                int c = np * 16 + ni * 8 + 2 * tig;
                Ms[r * E_LDM + c]           = silu_f(acc[mi][ni][0] + b2s[c]);
                Ms[r * E_LDM + c + 1]       = silu_f(acc[mi][ni][1] + b2s[c + 1]);
                Ms[(r + 8) * E_LDM + c]     = silu_f(acc[mi][ni][2] + b2s[c]);
                Ms[(r + 8) * E_LDM + c + 1] = silu_f(acc[mi][ni][3] + b2s[c + 1]);
            }
        }
        __syncthreads();

        // scatter: 2 threads per edge, 4 float4 RED each
        int e = tid >> 1;
        int cb = (tid & 1) * 16;
        int d = dsts[e];
        if (d >= 0) {
            #pragma unroll
            for (int q = 0; q < 4; q++) {
                float4 v = *(const float4*)&Ms[e * E_LDM + cb + q * 4];
                atomicAdd((float4*)&g_mi[(size_t)d * MD + cb + q * 4], v);
            }
        }
    }
}

// -------------------- LN stats --------------------
__global__ void stats_partial_kernel(const int* __restrict__ batch)
{
    __shared__ int s_lo, s_hi;
    __shared__ float rs[8], rs2[8];
    int g = blockIdx.x, part = blockIdx.y;
    int tid = threadIdx.x;
    if (tid == 0) { s_lo = lb_i(batch, NN, g); s_hi = lb_i(batch, NN, g + 1); }
    __syncthreads();
    int total = (s_hi - s_lo) * FP;
    int chunk = (total + 7) >> 3;
    int st = part * chunk;
    int en = st + chunk; if (en > total) en = total;
    const float* base = g_feats + (size_t)s_lo * FP;
    float s = 0.f, s2 = 0.f;
    for (int i = st + tid; i < en; i += 256) { float v = base[i]; s += v; s2 += v * v; }
    #pragma unroll
    for (int o = 16; o; o >>= 1) {
        s  += __shfl_down_sync(0xffffffffu, s, o);
        s2 += __shfl_down_sync(0xffffffffu, s2, o);
    }
    if ((tid & 31) == 0) { rs[tid >> 5] = s; rs2[tid >> 5] = s2; }
    __syncthreads();
    if (tid == 0) {
        float a = 0.f, b = 0.f;
        for (int i = 0; i < 8; i++) { a += rs[i]; b += rs2[i]; }
        atomicAdd(&g_sum[g], a); atomicAdd(&g_sum2[g], b);
    }
}

__global__ void stats_final_kernel(const int* __restrict__ batch)
{
    int g = threadIdx.x;
    if (g >= NG) return;
    int lo = lb_i(batch, NN, g), hi = lb_i(batch, NN, g + 1);
    int c = hi - lo; if (c < 1) c = 1;
    float denom = (float)c * 110.f;
    float mean = g_sum[g] / denom;
    float var = g_sum2[g] / denom - mean * mean;
    var = fmaxf(var, 0.f);
    g_mean[g] = mean;
    g_rstd[g] = rsqrtf(var + 1e-5f);
}

// ==================== fused node MLP: LN -> GEMM1 -> GEMM2 -> residual (512 thr) ====================
#define NJ_LDA 148
#define NJ_LDB1 136
#define NJ_LDH 132
#define NJ_LDB2 136
#define NJ_SMEM ((64 * NJ_LDA + 144 * NJ_LDB1 + 64 * NJ_LDH + 128 * NJ_LDB2) * 4)
__global__ void node_kernel(const int* __restrict__ batch,
    const float* __restrict__ nw1, const float* __restrict__ nb1,
    const float* __restrict__ nw2, const float* __restrict__ nb2,
    const float* __restrict__ lnw, const float* __restrict__ lnb, int l)
{
    extern __shared__ float sm[];
    uint32_t* Xs  = (uint32_t*)sm;                  // 64 x 148
    uint32_t* W1s = Xs + 64 * NJ_LDA;               // 144 x 136 (rows>=142 & cols>=128 zero)
    uint32_t* Hs  = W1s + 144 * NJ_LDB1;            // 64 x 132 (tf32 hid)
    uint32_t* W2s = Hs + 64 * NJ_LDH;               // 128 x 136 (cols>=110 zero)
    int tid = threadIdx.x;
    int m0 = blockIdx.x * 64;

    const float* w1b = nw1 + (size_t)l * NIN * NH;
    for (int i = tid; i < 144 * NJ_LDB1; i += 512) {
        int k = i / NJ_LDB1, c = i % NJ_LDB1;
        W1s[i] = (k < NIN && c < NH) ? f2tf(w1b[(size_t)k * NH + c]) : 0u;
    }
    const float* w2b = nw2 + (size_t)l * NH * NF;
    for (int i = tid; i < 128 * NJ_LDB2; i += 512) {
        int k = i / NJ_LDB2, c = i % NJ_LDB2;
        W2s[i] = (c < NF) ? f2tf(w2b[(size_t)k * NF + c]) : 0u;
    }
    for (int i = tid; i < 64 * NJ_LDA; i += 512) {
        int n = m0 + i / NJ_LDA, k = i % NJ_LDA;
        float v = 0.f;
        if (n < NN) {
            if (k < NF) {
                int gg = batch[n];
                float f = g_feats[(size_t)n * FP + k];
                v = lnw[l * NF + k] * ((f - g_mean[gg]) * g_rstd[gg]) + lnb[l * NF + k];
            } else if (k < NIN) {
                v = g_mi[(size_t)n * MD + (k - NF)];
            }
        }
        Xs[i] = f2tf(v);
    }
    __syncthreads();

    int w = tid >> 5, lane = tid & 31;
    int g = lane >> 2, tig = lane & 3;

    // ---- GEMM1: [64x144] @ [144x128], 16 warps: mp=w&1 (32 rows), np=w>>1 (16 cols)
    {
        int mp = w & 1, np = w >> 1;
        float acc[2][2][4];
        #pragma unroll
        for (int mi = 0; mi < 2; mi++)
            #pragma unroll
            for (int ni = 0; ni < 2; ni++)
                #pragma unroll
                for (int q = 0; q < 4; q++) acc[mi][ni][q] = 0.f;

        #pragma unroll 2
        for (int k0 = 0; k0 < 144; k0 += 8) {
            uint32_t a[2][4];
            #pragma unroll
            for (int mi = 0; mi < 2; mi++) {
                int r0 = mp * 32 + mi * 16;
                a[mi][0] = Xs[(r0 + g) * NJ_LDA + k0 + tig];
                a[mi][1] = Xs[(r0 + g + 8) * NJ_LDA + k0 + tig];
                a[mi][2] = Xs[(r0 + g) * NJ_LDA + k0 + tig + 4];
                a[mi][3] = Xs[(r0 + g + 8) * NJ_LDA + k0 + tig + 4];
            }
            uint32_t b[2][2];
            #pragma unroll
            for (int ni = 0; ni < 2; ni++) {
                int c0 = np * 16 + ni * 8 + g;
                b[ni][0] = W1s[(k0 + tig) * NJ_LDB1 + c0];
                b[ni][1] = W1s[(k0 + tig + 4) * NJ_LDB1 + c0];
            }
            #pragma unroll
            for (int mi = 0; mi < 2; mi++)
                #pragma unroll
                for (int ni = 0; ni < 2; ni++)
                    mma_tf32(acc[mi][ni], a[mi][0], a[mi][1], a[mi][2], a[mi][3], b[ni][0], b[ni][1]);
        }
        #pragma unroll
        for (int mi = 0; mi < 2; mi++) {
            int r = mp * 32 + mi * 16 + g;
            #pragma unroll
            for (int ni = 0; ni < 2; ni++) {
                int cg = np * 16 + ni * 8 + 2 * tig;
                float bb0 = nb1[l * NH + cg], bb1 = nb1[l * NH + cg + 1];
                Hs[r * NJ_LDH + cg]           = f2tf(silu_f(acc[mi][ni][0] + bb0));
                Hs[r * NJ_LDH + cg + 1]       = f2tf(silu_f(acc[mi][ni][1] + bb1));
                Hs[(r + 8) * NJ_LDH + cg]     = f2tf(silu_f(acc[mi][ni][2] + bb0));
                Hs[(r + 8) * NJ_LDH + cg + 1] = f2tf(silu_f(acc[mi][ni][3] + bb1));
            }
        }
    }
    __syncthreads();

    // ---- GEMM2: [64x128] @ [128x112], 16 warps: mp=w&3 (16 rows), np=w>>2 (32 cols)
    {
        int mp = w & 3, np = w >> 2;
        float acc[4][4];
        #pragma unroll
        for (int j = 0; j < 4; j++)
            #pragma unroll
            for (int q = 0; q < 4; q++) acc[j][q] = 0.f;

        #pragma unroll 2
        for (int k0 = 0; k0 < 128; k0 += 8) {
            uint32_t a0 = Hs[(mp * 16 + g) * NJ_LDH + k0 + tig];
            uint32_t a1 = Hs[(mp * 16 + g + 8) * NJ_LDH + k0 + tig];
            uint32_t a2 = Hs[(mp * 16 + g) * NJ_LDH + k0 + tig + 4];
            uint32_t a3 = Hs[(mp * 16 + g + 8) * NJ_LDH + k0 + tig + 4];
            uint32_t b[4][2];
            #pragma unroll
            for (int j = 0; j < 4; j++) {
                int c0 = np * 32 + j * 8 + g;
                b[j][0] = W2s[(k0 + tig) * NJ_LDB2 + c0];
                b[j][1] = W2s[(k0 + tig + 4) * NJ_LDB2 + c0];
            }
            #pragma unroll
            for (int j = 0; j < 4; j++)
                mma_tf32(acc[j], a0, a1, a2, a3, b[j][0], b[j][1]);
        }

        #pragma unroll
        for (int j = 0; j < 4; j++) {
            int c = np * 32 + j * 8 + 2 * tig;
            if (c >= NF) continue;
            float bb0 = nb2[l * NF + c], bb1 = nb2[l * NF + c + 1];
            int r = m0 + mp * 16 + g;
            if (r < NN) {
                float2 f = *(float2*)&g_feats[(size_t)r * FP + c];
                f.x += acc[j][0] + bb0; f.y += acc[j][1] + bb1;
                *(float2*)&g_feats[(size_t)r * FP + c] = f;
            }
            if (r + 8 < NN) {
                float2 f = *(float2*)&g_feats[(size_t)(r + 8) * FP + c];
                f.x += acc[j][2] + bb0; f.y += acc[j][3] + bb1;
                *(float2*)&g_feats[(size_t)(r + 8) * FP + c] = f;
            }
        }
    }

    // re-zero g_mi for next layer
    for (int i = tid; i < 64 * MD; i += 512) {
        int n = m0 + i / MD;
        if (n < NN) g_mi[(size_t)n * MD + (i % MD)] = 0.f;
    }
}

// -------------------- global mean pool --------------------
__global__ void pool_kernel(const int* __restrict__ batch, float* __restrict__ out)
{
    __shared__ int s_lo, s_hi;
    __shared__ float red[256];
    int g = blockIdx.x, tid = threadIdx.x;
    if (tid == 0) { s_lo = lb_i(batch, NN, g); s_hi = lb_i(batch, NN, g + 1); }
    __syncthreads();
    float s = 0.f;
    if (tid < 2 * FP) {
        int part = tid / FP;
        int k = tid % FP;
        for (int n = s_lo + part; n < s_hi; n += 2)
            s += g_feats[(size_t)n * FP + k];
    }
    red[tid] = s;
    __syncthreads();
    if (tid < NF) {
        int c = s_hi - s_lo; if (c < 1) c = 1;
        out[g * NF + tid] = (red[tid] + red[tid + FP]) / (float)c;
    }
}

// -------------------- launch --------------------
extern "C" void kernel_launch(void* const* d_in, const int* in_sizes, int n_in,
                              void* d_out, int out_size)
{
    const float* x     = (const float*)d_in[0];
    const int*   ei    = (const int*)  d_in[1];
    const float* eattr = (const float*)d_in[2];
    const float* pos   = (const float*)d_in[3];
    const int*   batch = (const int*)  d_in[4];
    const float* emb[10];
    for (int i = 0; i < 10; i++) emb[i] = (const float*)d_in[5 + i];
    const float* ew1 = (const float*)d_in[15];
    const float* eb1 = (const float*)d_in[16];
    const float* ew2 = (const float*)d_in[17];
    const float* eb2 = (const float*)d_in[18];
    const float* nw1 = (const float*)d_in[19];
    const float* nb1 = (const float*)d_in[20];
    const float* nw2 = (const float*)d_in[21];
    const float* nb2 = (const float*)d_in[22];
    const float* lnw = (const float*)d_in[23];
    const float* lnb = (const float*)d_in[24];
    float* out = (float*)d_out;

    cudaFuncSetAttribute(precompP_kernel, cudaFuncAttributeMaxDynamicSharedMemorySize, PP_SMEM);
    cudaFuncSetAttribute(edge_kernel,     cudaFuncAttributeMaxDynamicSharedMemorySize, EDGE_SMEM);
    cudaFuncSetAttribute(node_kernel,     cudaFuncAttributeMaxDynamicSharedMemorySize, NJ_SMEM);

    // Launch order chosen so edge_kernel (layer 0) is launch #4 -> ncu profiles it.
    embed_kernel<<<(NN * FP + 255) / 256, 256>>>(x, emb[0], emb[1], emb[2], emb[3],
                                                 emb[4], emb[5], emb[6], emb[7], emb[8], emb[9]);
    ea_kernel<<<(NE + 255) / 256, 256>>>(ei, eattr, pos);

    for (int l = 0; l < 2; l++) {
        precompP_kernel<<<dim3((NN + 63) / 64, 2), 256, PP_SMEM>>>(ew1, l);
        edge_kernel<<<E_GRID, 256, EDGE_SMEM>>>(ei, ew1, eb1, ew2, eb2, l);
        stats_partial_kernel<<<dim3(NG, 8), 256>>>(batch);
        stats_final_kernel<<<1, 64>>>(batch);
        node_kernel<<<(NN + 63) / 64, 512, NJ_SMEM>>>(batch, nw1, nb1, nw2, nb2, lnw, lnb, l);
    }
    pool_kernel<<<NG, 256>>>(batch, out);
}

// round 7
// speedup vs baseline: 1.4387x; 1.1627x over previous
#include <cuda_runtime.h>
#include <math.h>
#include <stdint.h>

#define NN   50000
#define NE   800000
#define NEL  850000
#define NG   64
#define FP   112
#define NF   110
#define MD   32
#define EH   128
#define NH   128
#define NIN  142
#define EFD  222

// -------- device scratch --------
__device__ float g_feats[NN * FP];
__device__ float g_P[(size_t)NN * 256];
__device__ float g_mi[NN * MD];
__device__ float g_ea[NE * 2];
__device__ float g_sum[NG], g_sum2[NG];
__device__ float g_mean[NG], g_rstd[NG];

__device__ __forceinline__ float silu_f(float x) {
    return x * (1.0f / (1.0f + __expf(-x)));
}
__device__ __forceinline__ uint32_t f2tf(float f) {
    uint32_t u; asm("cvt.rna.tf32.f32 %0, %1;" : "=r"(u) : "f"(f)); return u;
}
__device__ __forceinline__ void mma_tf32(float* d,
    uint32_t a0, uint32_t a1, uint32_t a2, uint32_t a3, uint32_t b0, uint32_t b1)
{
    asm volatile("mma.sync.aligned.m16n8k8.row.col.f32.tf32.tf32.f32 "
        "{%0,%1,%2,%3},{%4,%5,%6,%7},{%8,%9},{%0,%1,%2,%3};"
        : "+f"(d[0]), "+f"(d[1]), "+f"(d[2]), "+f"(d[3])
        : "r"(a0), "r"(a1), "r"(a2), "r"(a3), "r"(b0), "r"(b1));
}
__device__ __forceinline__ int lb_i(const int* __restrict__ a, int n, int v) {
    int lo = 0, hi = n;
    while (lo < hi) { int m = (lo + hi) >> 1; if (a[m] < v) lo = m + 1; else hi = m; }
    return lo;
}

// -------------------- embed (+ zero g_mi) --------------------
__global__ void embed_kernel(const float* __restrict__ x,
    const float* __restrict__ e0, const float* __restrict__ e1,
    const float* __restrict__ e2, const float* __restrict__ e3,
    const float* __restrict__ e4, const float* __restrict__ e5,
    const float* __restrict__ e6, const float* __restrict__ e7,
    const float* __restrict__ e8, const float* __restrict__ e9)
{
    long idx = (long)blockIdx.x * blockDim.x + threadIdx.x;
    if (idx < (long)NN * MD) g_mi[idx] = 0.f;
    if (idx >= (long)NN * FP) return;
    int n = (int)(idx / FP), k = (int)(idx % FP);
    float v = 0.f;
    if (k < 6) {
        int keep = (k == 0) ? 0 : (10 + k);
        v = x[n * 16 + keep];
    } else if (k < 38) {
        int code = (int)x[n * 16 + 1];
        v = e0[code * 32 + (k - 6)];
    } else if (k < 110) {
        int t = (k - 38) >> 3, c = (k - 38) & 7;
        int code = (int)x[n * 16 + 2 + t];
        const float* es[9] = {e1, e2, e3, e4, e5, e6, e7, e8, e9};
        v = es[t][code * 8 + c];
    }
    g_feats[idx] = v;
}

// -------------------- edge attr + rel dist --------------------
__global__ void ea_kernel(const int* __restrict__ ei,
                          const float* __restrict__ eattr,
                          const float* __restrict__ pos)
{
    int e = blockIdx.x * blockDim.x + threadIdx.x;
    if (e >= NE) return;
    int s = ei[e], d = ei[NE + e];
    float dx = pos[s * 3 + 0] - pos[d * 3 + 0];
    float dy = pos[s * 3 + 1] - pos[d * 3 + 1];
    float dz = pos[s * 3 + 2] - pos[d * 3 + 2];
    g_ea[2 * e + 0] = eattr[e];
    g_ea[2 * e + 1] = dx * dx + dy * dy + dz * dz;
}

// ==================== precompP: [64x112] @ [112x128] per half, tf32 MMA ====================
#define PP_LDA 116
#define PP_LDB 136
#define PP_SMEM ((64 * PP_LDA + 112 * PP_LDB) * 4)
__global__ void precompP_kernel(const float* __restrict__ w1, int l)
{
    extern __shared__ float sm[];
    uint32_t* Xs = (uint32_t*)sm;
    uint32_t* Ws = Xs + 64 * PP_LDA;
    int tid = threadIdx.x;
    int m0 = blockIdx.x * 64;
    int half = blockIdx.y;

    if (blockIdx.x == 0 && half == 0 && tid < 2 * NG) {
        if (tid < NG) g_sum[tid] = 0.f; else g_sum2[tid - NG] = 0.f;
    }

    const float* wbase = w1 + (size_t)l * EFD * EH + (size_t)half * 110 * EH;
    for (int i = tid; i < 112 * PP_LDB; i += 256) {
        int k = i / PP_LDB, c = i % PP_LDB;
        Ws[i] = (k < 110 && c < 128) ? f2tf(wbase[(size_t)k * EH + c]) : 0u;
    }
    for (int i = tid; i < 64 * PP_LDA; i += 256) {
        int r = i / PP_LDA, c = i % PP_LDA;
        int n = m0 + r;
        Xs[i] = (n < NN && c < FP) ? f2tf(g_feats[(size_t)n * FP + c]) : 0u;
    }
    __syncthreads();

    int w = tid >> 5, lane = tid & 31;
    int g = lane >> 2, tig = lane & 3;
    int mp = w & 1;
    int ng = w >> 1;
    float acc[2][4][4];
    #pragma unroll
    for (int mi = 0; mi < 2; mi++)
        #pragma unroll
        for (int j = 0; j < 4; j++)
            #pragma unroll
            for (int q = 0; q < 4; q++) acc[mi][j][q] = 0.f;

    #pragma unroll 2
    for (int k0 = 0; k0 < 112; k0 += 8) {
        uint32_t a[2][4];
        #pragma unroll
        for (int mi = 0; mi < 2; mi++) {
            int r0 = mp * 32 + mi * 16;
            a[mi][0] = Xs[(r0 + g) * PP_LDA + k0 + tig];
            a[mi][1] = Xs[(r0 + g + 8) * PP_LDA + k0 + tig];
            a[mi][2] = Xs[(r0 + g) * PP_LDA + k0 + tig + 4];
            a[mi][3] = Xs[(r0 + g + 8) * PP_LDA + k0 + tig + 4];
        }
        uint32_t b[4][2];
        #pragma unroll
        for (int j = 0; j < 4; j++) {
            int c0 = ng * 32 + j * 8 + g;
            b[j][0] = Ws[(k0 + tig) * PP_LDB + c0];
            b[j][1] = Ws[(k0 + tig + 4) * PP_LDB + c0];
        }
        #pragma unroll
        for (int mi = 0; mi < 2; mi++)
            #pragma unroll
            for (int j = 0; j < 4; j++)
                mma_tf32(acc[mi][j], a[mi][0], a[mi][1], a[mi][2], a[mi][3], b[j][0], b[j][1]);
    }

    #pragma unroll
    for (int mi = 0; mi < 2; mi++) {
        int r = m0 + mp * 32 + mi * 16 + g;
        #pragma unroll
        for (int j = 0; j < 4; j++) {
            int col = half * 128 + ng * 32 + j * 8 + 2 * tig;
            if (r < NN)
                *(float2*)&g_P[(size_t)r * 256 + col] = make_float2(acc[mi][j][0], acc[mi][j][1]);
            if (r + 8 < NN)
                *(float2*)&g_P[(size_t)(r + 8) * 256 + col] = make_float2(acc[mi][j][2], acc[mi][j][3]);
        }
    }
}

// ==================== persistent edge (512 thr): gather + tf32 MMA + scatter ====================
#define E_LDA 132
#define E_LDB 40
#define E_LDM 36
#define E_NT  ((NEL + 127) / 128)
#define E_GRID 296
#define EDGE_SMEM ((128 * E_LDA + 128 * E_LDB + 128 * 3 + 32 + 128 + 128 + 256) * 4)
__global__ void edge_kernel(const int* __restrict__ ei,
    const float* __restrict__ w1, const float* __restrict__ b1,
    const float* __restrict__ w2, const float* __restrict__ b2, int l)
{
    extern __shared__ float sm[];
    float* Hs   = sm;                       // 128 x 132 tf32 bits; reused as Ms 128 x 36
    float* W2s  = Hs + 128 * E_LDA;
    float* w220 = W2s + 128 * E_LDB;
    float* w221 = w220 + 128;
    float* b1s  = w221 + 128;
    float* b2s  = b1s + 128;
    float* ea0s = b2s + 32;
    float* dds  = ea0s + 128;
    int*   srcs = (int*)(dds + 128);
    int*   dsts = srcs + 128;
    uint32_t* HsU = (uint32_t*)Hs;
    uint32_t* WU  = (uint32_t*)W2s;
    float* Ms = Hs;

    int tid = threadIdx.x;
    const float* w1b = w1 + (size_t)l * EFD * EH;

    // weights resident for whole kernel
    if (tid < 128) {
        w220[tid] = w1b[220 * EH + tid];
        w221[tid] = w1b[221 * EH + tid];
        b1s[tid]  = b1[l * EH + tid];
    } else if (tid < 160) {
        b2s[tid - 128] = b2[l * MD + (tid - 128)];
    }
    for (int i = tid; i < 128 * 32; i += 512) {
        int k = i >> 5, c = i & 31;
        WU[k * E_LDB + c] = f2tf(w2[(size_t)l * EH * MD + i]);
    }

    int w = tid >> 5, lane = tid & 31;   // 16 warps
    int g = lane >> 2, tig = lane & 3;
    int mp = w & 7;          // 16-row strip: rows mp*16 .. +15
    int np = w >> 3;         // 16-col strip: cols np*16 .. +15

    for (int tile = blockIdx.x; tile < E_NT; tile += E_GRID) {
        int e0 = tile * 128;
        __syncthreads();    // smem safe to overwrite (also covers first-iter W load)
        if (tid < 128) {
            int e = e0 + tid;
            int s = -1, d = -1; float a = 0.f, dd = 0.f;
            if (e < NEL) {
                if (e < NE) { s = ei[e]; d = ei[NE + e]; a = g_ea[2 * e]; dd = g_ea[2 * e + 1]; }
                else        { s = d = e - NE; }
            }
            srcs[tid] = s; dsts[tid] = d; ea0s[tid] = a; dds[tid] = dd;
        }
        __syncthreads();

        // phase 1: H = silu(Pd[dst] + Ps[src] + ea*w220 + dist*w221 + b1)
        #pragma unroll
        for (int it = 0; it < 8; ++it) {
            int idx = it * 512 + tid;
            int e = idx >> 5;
            int k0 = (idx & 31) * 4;
            int d = dsts[e];
            uint4 u = make_uint4(0u, 0u, 0u, 0u);
            if (d >= 0) {
                int s = srcs[e];
                float4 pd = *(const float4*)&g_P[(size_t)d * 256 + k0];
                float4 ps = *(const float4*)&g_P[(size_t)s * 256 + 128 + k0];
                float a = ea0s[e], dd = dds[e];
                u.x = f2tf(silu_f(pd.x + ps.x + a * w220[k0 + 0] + dd * w221[k0 + 0] + b1s[k0 + 0]));
                u.y = f2tf(silu_f(pd.y + ps.y + a * w220[k0 + 1] + dd * w221[k0 + 1] + b1s[k0 + 1]));
                u.z = f2tf(silu_f(pd.z + ps.z + a * w220[k0 + 2] + dd * w221[k0 + 2] + b1s[k0 + 2]));
                u.w = f2tf(silu_f(pd.w + ps.w + a * w220[k0 + 3] + dd * w221[k0 + 3] + b1s[k0 + 3]));
            }
            *(uint4*)&HsU[e * E_LDA + k0] = u;
        }
        __syncthreads();

        // phase 2: [128x128] @ [128x32] tf32 MMA, 16 warps (mp: 8 row strips, np: 2 col strips)
        float acc[2][4];
        #pragma unroll
        for (int ni = 0; ni < 2; ni++)
            #pragma unroll
            for (int q = 0; q < 4; q++) acc[ni][q] = 0.f;

        #pragma unroll 4
        for (int k0 = 0; k0 < 128; k0 += 8) {
            uint32_t a0 = HsU[(mp * 16 + g) * E_LDA + k0 + tig];
            uint32_t a1 = HsU[(mp * 16 + g + 8) * E_LDA + k0 + tig];
            uint32_t a2 = HsU[(mp * 16 + g) * E_LDA + k0 + tig + 4];
            uint32_t a3 = HsU[(mp * 16 + g + 8) * E_LDA + k0 + tig + 4];
            uint32_t b[2][2];
            #pragma unroll
            for (int ni = 0; ni < 2; ni++) {
                int c0 = np * 16 + ni * 8 + g;
                b[ni][0] = WU[(k0 + tig) * E_LDB + c0];
                b[ni][1] = WU[(k0 + tig + 4) * E_LDB + c0];
            }
            #pragma unroll
            for (int ni = 0; ni < 2; ni++)
                mma_tf32(acc[ni], a0, a1, a2, a3, b[ni][0], b[ni][1]);
        }
        __syncthreads();   // done reading Hs; reuse as Ms

        {
            int r = mp * 16 + g;
            #pragma unroll
            for (int ni = 0; ni < 2; ni++) {
                int c = np * 16 + ni * 8 + 2 * tig;
                Ms[r * E_LDM + c]           = silu_f(acc[ni][0] + b2s[c]);
                Ms[r * E_LDM + c + 1]       = silu_f(acc[ni][1] + b2s[c + 1]);
                Ms[(r + 8) * E_LDM + c]     = silu_f(acc[ni][2] + b2s[c]);
                Ms[(r + 8) * E_LDM + c + 1] = silu_f(acc[ni][3] + b2s[c + 1]);
            }
        }
        __syncthreads();

        // scatter: 4 threads per edge, 2 float4 RED each
        int e = tid >> 2;
        int cb = (tid & 3) * 8;
        int d = dsts[e];
        if (d >= 0) {
            float4 v0 = *(const float4*)&Ms[e * E_LDM + cb];
            float4 v1 = *(const float4*)&Ms[e * E_LDM + cb + 4];
            atomicAdd((float4*)&g_mi[(size_t)d * MD + cb], v0);
            atomicAdd((float4*)&g_mi[(size_t)d * MD + cb + 4], v1);
        }
    }
}

// -------------------- LN stats --------------------
__global__ void stats_partial_kernel(const int* __restrict__ batch)
{
    __shared__ int s_lo, s_hi;
    __shared__ float rs[8], rs2[8];
    int g = blockIdx.x, part = blockIdx.y;
    int tid = threadIdx.x;
    if (tid == 0) { s_lo = lb_i(batch, NN, g); s_hi = lb_i(batch, NN, g + 1); }
    __syncthreads();
    int total = (s_hi - s_lo) * FP;
    int chunk = (total + 7) >> 3;
    int st = part * chunk;
    int en = st + chunk; if (en > total) en = total;
    const float* base = g_feats + (size_t)s_lo * FP;
    float s = 0.f, s2 = 0.f;
    for (int i = st + tid; i < en; i += 256) { float v = base[i]; s += v; s2 += v * v; }
    #pragma unroll
    for (int o = 16; o; o >>= 1) {
        s  += __shfl_down_sync(0xffffffffu, s, o);
        s2 += __shfl_down_sync(0xffffffffu, s2, o);
    }
    if ((tid & 31) == 0) { rs[tid >> 5] = s; rs2[tid >> 5] = s2; }
    __syncthreads();
    if (tid == 0) {
        float a = 0.f, b = 0.f;
        for (int i = 0; i < 8; i++) { a += rs[i]; b += rs2[i]; }
        atomicAdd(&g_sum[g], a); atomicAdd(&g_sum2[g], b);
    }
}

__global__ void stats_final_kernel(const int* __restrict__ batch)
{
    int g = threadIdx.x;
    if (g >= NG) return;
    int lo = lb_i(batch, NN, g), hi = lb_i(batch, NN, g + 1);
    int c = hi - lo; if (c < 1) c = 1;
    float denom = (float)c * 110.f;
    float mean = g_sum[g] / denom;
    float var = g_sum2[g] / denom - mean * mean;
    var = fmaxf(var, 0.f);
    g_mean[g] = mean;
    g_rstd[g] = rsqrtf(var + 1e-5f);
}

// ==================== fused node MLP: LN -> GEMM1 -> GEMM2 -> residual (512 thr) ====================
#define NJ_LDA 148
#define NJ_LDB1 136
#define NJ_LDH 132
#define NJ_LDB2 136
#define NJ_SMEM ((64 * NJ_LDA + 144 * NJ_LDB1 + 64 * NJ_LDH + 128 * NJ_LDB2) * 4)
__global__ void node_kernel(const int* __restrict__ batch,
    const float* __restrict__ nw1, const float* __restrict__ nb1,
    const float* __restrict__ nw2, const float* __restrict__ nb2,
    const float* __restrict__ lnw, const float* __restrict__ lnb, int l)
{
    extern __shared__ float sm[];
    uint32_t* Xs  = (uint32_t*)sm;                  // 64 x 148
    uint32_t* W1s = Xs + 64 * NJ_LDA;               // 144 x 136
    uint32_t* Hs  = W1s + 144 * NJ_LDB1;            // 64 x 132
    uint32_t* W2s = Hs + 64 * NJ_LDH;               // 128 x 136
    int tid = threadIdx.x;
    int m0 = blockIdx.x * 64;

    const float* w1b = nw1 + (size_t)l * NIN * NH;
    for (int i = tid; i < 144 * NJ_LDB1; i += 512) {
        int k = i / NJ_LDB1, c = i % NJ_LDB1;
        W1s[i] = (k < NIN && c < NH) ? f2tf(w1b[(size_t)k * NH + c]) : 0u;
    }
    const float* w2b = nw2 + (size_t)l * NH * NF;
    for (int i = tid; i < 128 * NJ_LDB2; i += 512) {
        int k = i / NJ_LDB2, c = i % NJ_LDB2;
        W2s[i] = (c < NF) ? f2tf(w2b[(size_t)k * NF + c]) : 0u;
    }
    for (int i = tid; i < 64 * NJ_LDA; i += 512) {
        int n = m0 + i / NJ_LDA, k = i % NJ_LDA;
        float v = 0.f;
        if (n < NN) {
            if (k < NF) {
                int gg = batch[n];
                float f = g_feats[(size_t)n * FP + k];
                v = lnw[l * NF + k] * ((f - g_mean[gg]) * g_rstd[gg]) + lnb[l * NF + k];
            } else if (k < NIN) {
                v = g_mi[(size_t)n * MD + (k - NF)];
            }
        }
        Xs[i] = f2tf(v);
    }
    __syncthreads();

    int w = tid >> 5, lane = tid & 31;
    int g = lane >> 2, tig = lane & 3;

    // ---- GEMM1: [64x144] @ [144x128], 16 warps: mp=w&1 (32 rows), np=w>>1 (16 cols)
    {
        int mp = w & 1, np = w >> 1;
        float acc[2][2][4];
        #pragma unroll
        for (int mi = 0; mi < 2; mi++)
            #pragma unroll
            for (int ni = 0; ni < 2; ni++)
                #pragma unroll
                for (int q = 0; q < 4; q++) acc[mi][ni][q] = 0.f;

        #pragma unroll 2
        for (int k0 = 0; k0 < 144; k0 += 8) {
            uint32_t a[2][4];
            #pragma unroll
            for (int mi = 0; mi < 2; mi++) {
                int r0 = mp * 32 + mi * 16;
                a[mi][0] = Xs[(r0 + g) * NJ_LDA + k0 + tig];
                a[mi][1] = Xs[(r0 + g + 8) * NJ_LDA + k0 + tig];
                a[mi][2] = Xs[(r0 + g) * NJ_LDA + k0 + tig + 4];
                a[mi][3] = Xs[(r0 + g + 8) * NJ_LDA + k0 + tig + 4];
            }
            uint32_t b[2][2];
            #pragma unroll
            for (int ni = 0; ni < 2; ni++) {
                int c0 = np * 16 + ni * 8 + g;
                b[ni][0] = W1s[(k0 + tig) * NJ_LDB1 + c0];
                b[ni][1] = W1s[(k0 + tig + 4) * NJ_LDB1 + c0];
            }
            #pragma unroll
            for (int mi = 0; mi < 2; mi++)
                #pragma unroll
                for (int ni = 0; ni < 2; ni++)
                    mma_tf32(acc[mi][ni], a[mi][0], a[mi][1], a[mi][2], a[mi][3], b[ni][0], b[ni][1]);
        }
        #pragma unroll
        for (int mi = 0; mi < 2; mi++) {
            int r = mp * 32 + mi * 16 + g;
            #pragma unroll
            for (int ni = 0; ni < 2; ni++) {
                int cg = np * 16 + ni * 8 + 2 * tig;
                float bb0 = nb1[l * NH + cg], bb1 = nb1[l * NH + cg + 1];
                Hs[r * NJ_LDH + cg]           = f2tf(silu_f(acc[mi][ni][0] + bb0));
                Hs[r * NJ_LDH + cg + 1]       = f2tf(silu_f(acc[mi][ni][1] + bb1));
                Hs[(r + 8) * NJ_LDH + cg]     = f2tf(silu_f(acc[mi][ni][2] + bb0));
                Hs[(r + 8) * NJ_LDH + cg + 1] = f2tf(silu_f(acc[mi][ni][3] + bb1));
            }
        }
    }
    __syncthreads();

    // ---- GEMM2: [64x128] @ [128x112], 16 warps: mp=w&3 (16 rows), np=w>>2 (32 cols)
    {
        int mp = w & 3, np = w >> 2;
        float acc[4][4];
        #pragma unroll
        for (int j = 0; j < 4; j++)
            #pragma unroll
            for (int q = 0; q < 4; q++) acc[j][q] = 0.f;

        #pragma unroll 2
        for (int k0 = 0; k0 < 128; k0 += 8) {
            uint32_t a0 = Hs[(mp * 16 + g) * NJ_LDH + k0 + tig];
            uint32_t a1 = Hs[(mp * 16 + g + 8) * NJ_LDH + k0 + tig];
            uint32_t a2 = Hs[(mp * 16 + g) * NJ_LDH + k0 + tig + 4];
            uint32_t a3 = Hs[(mp * 16 + g + 8) * NJ_LDH + k0 + tig + 4];
            uint32_t b[4][2];
            #pragma unroll
            for (int j = 0; j < 4; j++) {
                int c0 = np * 32 + j * 8 + g;
                b[j][0] = W2s[(k0 + tig) * NJ_LDB2 + c0];
                b[j][1] = W2s[(k0 + tig + 4) * NJ_LDB2 + c0];
            }
            #pragma unroll
            for (int j = 0; j < 4; j++)
                mma_tf32(acc[j], a0, a1, a2, a3, b[j][0], b[j][1]);
        }

        #pragma unroll
        for (int j = 0; j < 4; j++) {
            int c = np * 32 + j * 8 + 2 * tig;
            if (c >= NF) continue;
            float bb0 = nb2[l * NF + c], bb1 = nb2[l * NF + c + 1];
            int r = m0 + mp * 16 + g;
            if (r < NN) {
                float2 f = *(float2*)&g_feats[(size_t)r * FP + c];
                f.x += acc[j][0] + bb0; f.y += acc[j][1] + bb1;
                *(float2*)&g_feats[(size_t)r * FP + c] = f;
            }
            if (r + 8 < NN) {
                float2 f = *(float2*)&g_feats[(size_t)(r + 8) * FP + c];
                f.x += acc[j][2] + bb0; f.y += acc[j][3] + bb1;
                *(float2*)&g_feats[(size_t)(r + 8) * FP + c] = f;
            }
        }
    }

    // re-zero g_mi for next layer
    for (int i = tid; i < 64 * MD; i += 512) {
        int n = m0 + i / MD;
        if (n < NN) g_mi[(size_t)n * MD + (i % MD)] = 0.f;
    }
}

// -------------------- global mean pool --------------------
__global__ void pool_kernel(const int* __restrict__ batch, float* __restrict__ out)
{
    __shared__ int s_lo, s_hi;
    __shared__ float red[256];
    int g = blockIdx.x, tid = threadIdx.x;
    if (tid == 0) { s_lo = lb_i(batch, NN, g); s_hi = lb_i(batch, NN, g + 1); }
    __syncthreads();
    float s = 0.f;
    if (tid < 2 * FP) {
        int part = tid / FP;
        int k = tid % FP;
        for (int n = s_lo + part; n < s_hi; n += 2)
            s += g_feats[(size_t)n * FP + k];
    }
    red[tid] = s;
    __syncthreads();
    if (tid < NF) {
        int c = s_hi - s_lo; if (c < 1) c = 1;
        out[g * NF + tid] = (red[tid] + red[tid + FP]) / (float)c;
    }
}

// -------------------- launch --------------------
extern "C" void kernel_launch(void* const* d_in, const int* in_sizes, int n_in,
                              void* d_out, int out_size)
{
    const float* x     = (const float*)d_in[0];
    const int*   ei    = (const int*)  d_in[1];
    const float* eattr = (const float*)d_in[2];
    const float* pos   = (const float*)d_in[3];
    const int*   batch = (const int*)  d_in[4];
    const float* emb[10];
    for (int i = 0; i < 10; i++) emb[i] = (const float*)d_in[5 + i];
    const float* ew1 = (const float*)d_in[15];
    const float* eb1 = (const float*)d_in[16];
    const float* ew2 = (const float*)d_in[17];
    const float* eb2 = (const float*)d_in[18];
    const float* nw1 = (const float*)d_in[19];
    const float* nb1 = (const float*)d_in[20];
    const float* nw2 = (const float*)d_in[21];
    const float* nb2 = (const float*)d_in[22];
    const float* lnw = (const float*)d_in[23];
    const float* lnb = (const float*)d_in[24];
    float* out = (float*)d_out;

    cudaFuncSetAttribute(precompP_kernel, cudaFuncAttributeMaxDynamicSharedMemorySize, PP_SMEM);
    cudaFuncSetAttribute(edge_kernel,     cudaFuncAttributeMaxDynamicSharedMemorySize, EDGE_SMEM);
    cudaFuncSetAttribute(node_kernel,     cudaFuncAttributeMaxDynamicSharedMemorySize, NJ_SMEM);

    embed_kernel<<<(NN * FP + 255) / 256, 256>>>(x, emb[0], emb[1], emb[2], emb[3],
                                                 emb[4], emb[5], emb[6], emb[7], emb[8], emb[9]);
    ea_kernel<<<(NE + 255) / 256, 256>>>(ei, eattr, pos);

    for (int l = 0; l < 2; l++) {
        precompP_kernel<<<dim3((NN + 63) / 64, 2), 256, PP_SMEM>>>(ew1, l);
        edge_kernel<<<E_GRID, 512, EDGE_SMEM>>>(ei, ew1, eb1, ew2, eb2, l);
        stats_partial_kernel<<<dim3(NG, 8), 256>>>(batch);
        stats_final_kernel<<<1, 64>>>(batch);
        node_kernel<<<(NN + 63) / 64, 512, NJ_SMEM>>>(batch, nw1, nb1, nw2, nb2, lnw, lnb, l);
    }
    pool_kernel<<<NG, 256>>>(batch, out);
}

// round 8
// speedup vs baseline: 1.4810x; 1.0294x over previous
#include <cuda_runtime.h>
#include <math.h>
#include <stdint.h>

#define NN   50000
#define NE   800000
#define NEL  850000
#define NG   64
#define FP   112
#define NF   110
#define MD   32
#define EH   128
#define NH   128
#define NIN  142
#define EFD  222

// -------- device scratch --------
__device__ float g_feats[NN * FP];
__device__ float g_P[(size_t)NN * 256];
__device__ float g_mi[NN * MD];
__device__ float g_ea[NE * 2];
__device__ float g_sum[NG], g_sum2[NG];
__device__ float g_mean[NG], g_rstd[NG];

__device__ __forceinline__ float silu_f(float x) {
    return x * (1.0f / (1.0f + __expf(-x)));
}
__device__ __forceinline__ uint32_t f2tf(float f) {
    uint32_t u; asm("cvt.rna.tf32.f32 %0, %1;" : "=r"(u) : "f"(f)); return u;
}
__device__ __forceinline__ void mma_tf32(float* d,
    uint32_t a0, uint32_t a1, uint32_t a2, uint32_t a3, uint32_t b0, uint32_t b1)
{
    asm volatile("mma.sync.aligned.m16n8k8.row.col.f32.tf32.tf32.f32 "
        "{%0,%1,%2,%3},{%4,%5,%6,%7},{%8,%9},{%0,%1,%2,%3};"
        : "+f"(d[0]), "+f"(d[1]), "+f"(d[2]), "+f"(d[3])
        : "r"(a0), "r"(a1), "r"(a2), "r"(a3), "r"(b0), "r"(b1));
}
__device__ __forceinline__ void ldsm_x4(uint32_t& r0, uint32_t& r1, uint32_t& r2, uint32_t& r3,
                                        uint32_t saddr)
{
    asm volatile("ldmatrix.sync.aligned.m8n8.x4.shared.b16 {%0,%1,%2,%3}, [%4];"
        : "=r"(r0), "=r"(r1), "=r"(r2), "=r"(r3) : "r"(saddr));
}
__device__ __forceinline__ int lb_i(const int* __restrict__ a, int n, int v) {
    int lo = 0, hi = n;
    while (lo < hi) { int m = (lo + hi) >> 1; if (a[m] < v) lo = m + 1; else hi = m; }
    return lo;
}

// -------------------- embed (+ zero g_mi) --------------------
__global__ void embed_kernel(const float* __restrict__ x,
    const float* __restrict__ e0, const float* __restrict__ e1,
    const float* __restrict__ e2, const float* __restrict__ e3,
    const float* __restrict__ e4, const float* __restrict__ e5,
    const float* __restrict__ e6, const float* __restrict__ e7,
    const float* __restrict__ e8, const float* __restrict__ e9)
{
    long idx = (long)blockIdx.x * blockDim.x + threadIdx.x;
    if (idx < (long)NN * MD) g_mi[idx] = 0.f;
    if (idx >= (long)NN * FP) return;
    int n = (int)(idx / FP), k = (int)(idx % FP);
    float v = 0.f;
    if (k < 6) {
        int keep = (k == 0) ? 0 : (10 + k);
        v = x[n * 16 + keep];
    } else if (k < 38) {
        int code = (int)x[n * 16 + 1];
        v = e0[code * 32 + (k - 6)];
    } else if (k < 110) {
        int t = (k - 38) >> 3, c = (k - 38) & 7;
        int code = (int)x[n * 16 + 2 + t];
        const float* es[9] = {e1, e2, e3, e4, e5, e6, e7, e8, e9};
        v = es[t][code * 8 + c];
    }
    g_feats[idx] = v;
}

// -------------------- edge attr + rel dist --------------------
__global__ void ea_kernel(const int* __restrict__ ei,
                          const float* __restrict__ eattr,
                          const float* __restrict__ pos)
{
    int e = blockIdx.x * blockDim.x + threadIdx.x;
    if (e >= NE) return;
    int s = ei[e], d = ei[NE + e];
    float dx = pos[s * 3 + 0] - pos[d * 3 + 0];
    float dy = pos[s * 3 + 1] - pos[d * 3 + 1];
    float dz = pos[s * 3 + 2] - pos[d * 3 + 2];
    g_ea[2 * e + 0] = eattr[e];
    g_ea[2 * e + 1] = dx * dx + dy * dy + dz * dz;
}

// ==================== precompP: [64x112] @ [112x128] per half, tf32 MMA ====================
#define PP_LDA 116
#define PP_LDB 136
#define PP_SMEM ((64 * PP_LDA + 112 * PP_LDB) * 4)
__global__ void precompP_kernel(const float* __restrict__ w1, int l)
{
    extern __shared__ float sm[];
    uint32_t* Xs = (uint32_t*)sm;
    uint32_t* Ws = Xs + 64 * PP_LDA;
    int tid = threadIdx.x;
    int m0 = blockIdx.x * 64;
    int half = blockIdx.y;

    if (blockIdx.x == 0 && half == 0 && tid < 2 * NG) {
        if (tid < NG) g_sum[tid] = 0.f; else g_sum2[tid - NG] = 0.f;
    }

    const float* wbase = w1 + (size_t)l * EFD * EH + (size_t)half * 110 * EH;
    for (int i = tid; i < 112 * PP_LDB; i += 256) {
        int k = i / PP_LDB, c = i % PP_LDB;
        Ws[i] = (k < 110 && c < 128) ? f2tf(wbase[(size_t)k * EH + c]) : 0u;
    }
    for (int i = tid; i < 64 * PP_LDA; i += 256) {
        int r = i / PP_LDA, c = i % PP_LDA;
        int n = m0 + r;
        Xs[i] = (n < NN && c < FP) ? f2tf(g_feats[(size_t)n * FP + c]) : 0u;
    }
    __syncthreads();

    int w = tid >> 5, lane = tid & 31;
    int g = lane >> 2, tig = lane & 3;
    int mp = w & 1;
    int ng = w >> 1;
    float acc[2][4][4];
    #pragma unroll
    for (int mi = 0; mi < 2; mi++)
        #pragma unroll
        for (int j = 0; j < 4; j++)
            #pragma unroll
            for (int q = 0; q < 4; q++) acc[mi][j][q] = 0.f;

    #pragma unroll 2
    for (int k0 = 0; k0 < 112; k0 += 8) {
        uint32_t a[2][4];
        #pragma unroll
        for (int mi = 0; mi < 2; mi++) {
            int r0 = mp * 32 + mi * 16;
            a[mi][0] = Xs[(r0 + g) * PP_LDA + k0 + tig];
            a[mi][1] = Xs[(r0 + g + 8) * PP_LDA + k0 + tig];
            a[mi][2] = Xs[(r0 + g) * PP_LDA + k0 + tig + 4];
            a[mi][3] = Xs[(r0 + g + 8) * PP_LDA + k0 + tig + 4];
        }
        uint32_t b[4][2];
        #pragma unroll
        for (int j = 0; j < 4; j++) {
            int c0 = ng * 32 + j * 8 + g;
            b[j][0] = Ws[(k0 + tig) * PP_LDB + c0];
            b[j][1] = Ws[(k0 + tig + 4) * PP_LDB + c0];
        }
        #pragma unroll
        for (int mi = 0; mi < 2; mi++)
            #pragma unroll
            for (int j = 0; j < 4; j++)
                mma_tf32(acc[mi][j], a[mi][0], a[mi][1], a[mi][2], a[mi][3], b[j][0], b[j][1]);
    }

    #pragma unroll
    for (int mi = 0; mi < 2; mi++) {
        int r = m0 + mp * 32 + mi * 16 + g;
        #pragma unroll
        for (int j = 0; j < 4; j++) {
            int col = half * 128 + ng * 32 + j * 8 + 2 * tig;
            if (r < NN)
                *(float2*)&g_P[(size_t)r * 256 + col] = make_float2(acc[mi][j][0], acc[mi][j][1]);
            if (r + 8 < NN)
                *(float2*)&g_P[(size_t)(r + 8) * 256 + col] = make_float2(acc[mi][j][2], acc[mi][j][3]);
        }
    }
}

// ==================== persistent edge (512 thr): gather + tf32 MMA (ldmatrix) + scatter ====================
#define E_LDA 132
#define E_LDM 36
#define E_NT  ((NEL + 127) / 128)
#define E_GRID 296
// floats: Hs 128*132 | WT 32*132 | b2s 32 | eds 128*int4
#define EDGE_SMEM ((128 * E_LDA + 32 * E_LDA + 32 + 128 * 4) * 4)
__global__ void __launch_bounds__(512, 2) edge_kernel(const int* __restrict__ ei,
    const float* __restrict__ w1, const float* __restrict__ b1,
    const float* __restrict__ w2, const float* __restrict__ b2, int l)
{
    extern __shared__ float sm[];
    float* Hs  = sm;                        // 128 x 132 (tf32 bits); reused as Ms 128 x 36
    float* WTs = Hs + 128 * E_LDA;          // 32(c) x 132(k) transposed W2 (tf32 bits)
    float* b2s = WTs + 32 * E_LDA;
    int4*  eds = (int4*)(b2s + 32);         // (src, dst, ea_bits, dist_bits) per edge
    uint32_t* HsU = (uint32_t*)Hs;
    float* Ms = Hs;

    int tid = threadIdx.x;
    const float* w1b = w1 + (size_t)l * EFD * EH;

    // per-thread loop-invariant phase-1 constants (k0 fixed per thread)
    int k0 = (tid & 31) * 4;
    float4 cw0 = *(const float4*)&w1b[220 * EH + k0];
    float4 cw1 = *(const float4*)&w1b[221 * EH + k0];
    float4 cb1 = *(const float4*)&b1[l * EH + k0];

    if (tid < 32) b2s[tid] = b2[l * MD + tid];
    // WT: [c][k] transposed W2, tf32 bits
    for (int i = tid; i < 128 * 32; i += 512) {
        int k = i >> 5, c = i & 31;
        WTs[c * E_LDA + k] = __uint_as_float(f2tf(w2[(size_t)l * EH * MD + i]));
    }

    int wid = tid >> 5, lane = tid & 31;   // 16 warps
    int g = lane >> 2, tig = lane & 3;
    int mp = wid & 7;          // 16-row strip
    int np = wid >> 3;         // 16-col strip

    // ldmatrix lane addressing (row part fixed, add 32B per k-step)
    uint32_t HsS = (uint32_t)__cvta_generic_to_shared(Hs);
    uint32_t WTS = (uint32_t)__cvta_generic_to_shared(WTs);
    int lrow = ((lane >> 3) & 1) * 8 + (lane & 7);
    int lcol = (lane >> 4) * 4;
    uint32_t aBase = HsS + (uint32_t)(((mp * 16 + lrow) * E_LDA + lcol) * 4);
    uint32_t bBase = WTS + (uint32_t)(((np * 16 + lrow) * E_LDA + lcol) * 4);

    for (int tile = blockIdx.x; tile < E_NT; tile += E_GRID) {
        int e0 = tile * 128;
        __syncthreads();    // smem safe to overwrite (also covers first-iter WT load)
        if (tid < 128) {
            int e = e0 + tid;
            int s = -1, d = -1; float a = 0.f, dd = 0.f;
            if (e < NEL) {
                if (e < NE) { s = ei[e]; d = ei[NE + e]; a = g_ea[2 * e]; dd = g_ea[2 * e + 1]; }
                else        { s = d = e - NE; }
            }
            eds[tid] = make_int4(s, d, __float_as_int(a), __float_as_int(dd));
        }
        __syncthreads();

        // phase 1: H = silu(Pd[dst] + Ps[src] + ea*w220 + dist*w221 + b1), one edge per warp-iter
        #pragma unroll
        for (int it = 0; it < 8; ++it) {
            int e = it * 16 + wid;
            int4 ed = eds[e];
            uint4 u = make_uint4(0u, 0u, 0u, 0u);
            if (ed.y >= 0) {
                float4 pd = *(const float4*)(g_P + (ed.y * 256 + k0));
                float4 ps = *(const float4*)(g_P + (ed.x * 256 + 128 + k0));
                float a = __int_as_float(ed.z), dd = __int_as_float(ed.w);
                u.x = f2tf(silu_f(pd.x + ps.x + a * cw0.x + dd * cw1.x + cb1.x));
                u.y = f2tf(silu_f(pd.y + ps.y + a * cw0.y + dd * cw1.y + cb1.y));
                u.z = f2tf(silu_f(pd.z + ps.z + a * cw0.z + dd * cw1.z + cb1.z));
                u.w = f2tf(silu_f(pd.w + ps.w + a * cw0.w + dd * cw1.w + cb1.w));
            }
            *(uint4*)&HsU[e * E_LDA + k0] = u;
        }
        __syncthreads();

        // phase 2: [128x128] @ [128x32] tf32 MMA via ldmatrix
        float acc[2][4];
        #pragma unroll
        for (int ni = 0; ni < 2; ni++)
            #pragma unroll
            for (int q = 0; q < 4; q++) acc[ni][q] = 0.f;

        #pragma unroll 4
        for (int ks = 0; ks < 16; ++ks) {
            uint32_t a0, a1, a2, a3, b00, b10, b01, b11;
            ldsm_x4(a0, a1, a2, a3, aBase + ks * 32);
            ldsm_x4(b00, b10, b01, b11, bBase + ks * 32);
            mma_tf32(acc[0], a0, a1, a2, a3, b00, b01);
            mma_tf32(acc[1], a0, a1, a2, a3, b10, b11);
        }
        __syncthreads();   // done reading Hs; reuse as Ms

        {
            int r = mp * 16 + g;
            #pragma unroll
            for (int ni = 0; ni < 2; ni++) {
                int c = np * 16 + ni * 8 + 2 * tig;
                Ms[r * E_LDM + c]           = silu_f(acc[ni][0] + b2s[c]);
                Ms[r * E_LDM + c + 1]       = silu_f(acc[ni][1] + b2s[c + 1]);
                Ms[(r + 8) * E_LDM + c]     = silu_f(acc[ni][2] + b2s[c]);
                Ms[(r + 8) * E_LDM + c + 1] = silu_f(acc[ni][3] + b2s[c + 1]);
            }
        }
        __syncthreads();

        // scatter: 4 threads per edge, 2 float4 RED each
        int e = tid >> 2;
        int cb = (tid & 3) * 8;
        int d = eds[e].y;
        if (d >= 0) {
            float4 v0 = *(const float4*)&Ms[e * E_LDM + cb];
            float4 v1 = *(const float4*)&Ms[e * E_LDM + cb + 4];
            atomicAdd((float4*)(g_mi + (d * MD + cb)), v0);
            atomicAdd((float4*)(g_mi + (d * MD + cb + 4)), v1);
        }
    }
}

// -------------------- LN stats --------------------
__global__ void stats_partial_kernel(const int* __restrict__ batch)
{
    __shared__ int s_lo, s_hi;
    __shared__ float rs[8], rs2[8];
    int g = blockIdx.x, part = blockIdx.y;
    int tid = threadIdx.x;
    if (tid == 0) { s_lo = lb_i(batch, NN, g); s_hi = lb_i(batch, NN, g + 1); }
    __syncthreads();
    int total = (s_hi - s_lo) * FP;
    int chunk = (total + 7) >> 3;
    int st = part * chunk;
    int en = st + chunk; if (en > total) en = total;
    const float* base = g_feats + (size_t)s_lo * FP;
    float s = 0.f, s2 = 0.f;
    for (int i = st + tid; i < en; i += 256) { float v = base[i]; s += v; s2 += v * v; }
    #pragma unroll
    for (int o = 16; o; o >>= 1) {
        s  += __shfl_down_sync(0xffffffffu, s, o);
        s2 += __shfl_down_sync(0xffffffffu, s2, o);
    }
    if ((tid & 31) == 0) { rs[tid >> 5] = s; rs2[tid >> 5] = s2; }
    __syncthreads();
    if (tid == 0) {
        float a = 0.f, b = 0.f;
        for (int i = 0; i < 8; i++) { a += rs[i]; b += rs2[i]; }
        atomicAdd(&g_sum[g], a); atomicAdd(&g_sum2[g], b);
    }
}

__global__ void stats_final_kernel(const int* __restrict__ batch)
{
    int g = threadIdx.x;
    if (g >= NG) return;
    int lo = lb_i(batch, NN, g), hi = lb_i(batch, NN, g + 1);
    int c = hi - lo; if (c < 1) c = 1;
    float denom = (float)c * 110.f;
    float mean = g_sum[g] / denom;
    float var = g_sum2[g] / denom - mean * mean;
    var = fmaxf(var, 0.f);
    g_mean[g] = mean;
    g_rstd[g] = rsqrtf(var + 1e-5f);
}

// ==================== fused node MLP: LN -> GEMM1 -> GEMM2 -> residual (512 thr) ====================
#define NJ_LDA 148
#define NJ_LDB1 136
#define NJ_LDH 132
#define NJ_LDB2 136
#define NJ_SMEM ((64 * NJ_LDA + 144 * NJ_LDB1 + 64 * NJ_LDH + 128 * NJ_LDB2) * 4)
__global__ void node_kernel(const int* __restrict__ batch,
    const float* __restrict__ nw1, const float* __restrict__ nb1,
    const float* __restrict__ nw2, const float* __restrict__ nb2,
    const float* __restrict__ lnw, const float* __restrict__ lnb, int l)
{
    extern __shared__ float sm[];
    uint32_t* Xs  = (uint32_t*)sm;                  // 64 x 148
    uint32_t* W1s = Xs + 64 * NJ_LDA;               // 144 x 136
    uint32_t* Hs  = W1s + 144 * NJ_LDB1;            // 64 x 132
    uint32_t* W2s = Hs + 64 * NJ_LDH;               // 128 x 136
    int tid = threadIdx.x;
    int m0 = blockIdx.x * 64;

    const float* w1b = nw1 + (size_t)l * NIN * NH;
    for (int i = tid; i < 144 * NJ_LDB1; i += 512) {
        int k = i / NJ_LDB1, c = i % NJ_LDB1;
        W1s[i] = (k < NIN && c < NH) ? f2tf(w1b[(size_t)k * NH + c]) : 0u;
    }
    const float* w2b = nw2 + (size_t)l * NH * NF;
    for (int i = tid; i < 128 * NJ_LDB2; i += 512) {
        int k = i / NJ_LDB2, c = i % NJ_LDB2;
        W2s[i] = (c < NF) ? f2tf(w2b[(size_t)k * NF + c]) : 0u;
    }
    for (int i = tid; i < 64 * NJ_LDA; i += 512) {
        int n = m0 + i / NJ_LDA, k = i % NJ_LDA;
        float v = 0.f;
        if (n < NN) {
            if (k < NF) {
                int gg = batch[n];
                float f = g_feats[(size_t)n * FP + k];
                v = lnw[l * NF + k] * ((f - g_mean[gg]) * g_rstd[gg]) + lnb[l * NF + k];
            } else if (k < NIN) {
                v = g_mi[(size_t)n * MD + (k - NF)];
            }
        }
        Xs[i] = f2tf(v);
    }
    __syncthreads();

    int w = tid >> 5, lane = tid & 31;
    int g = lane >> 2, tig = lane & 3;

    // ---- GEMM1: [64x144] @ [144x128], 16 warps: mp=w&1 (32 rows), np=w>>1 (16 cols)
    {
        int mp = w & 1, np = w >> 1;
        float acc[2][2][4];
        #pragma unroll
        for (int mi = 0; mi < 2; mi++)
            #pragma unroll
            for (int ni = 0; ni < 2; ni++)
                #pragma unroll
                for (int q = 0; q < 4; q++) acc[mi][ni][q] = 0.f;

        #pragma unroll 2
        for (int k0 = 0; k0 < 144; k0 += 8) {
            uint32_t a[2][4];
            #pragma unroll
            for (int mi = 0; mi < 2; mi++) {
                int r0 = mp * 32 + mi * 16;
                a[mi][0] = Xs[(r0 + g) * NJ_LDA + k0 + tig];
                a[mi][1] = Xs[(r0 + g + 8) * NJ_LDA + k0 + tig];
                a[mi][2] = Xs[(r0 + g) * NJ_LDA + k0 + tig + 4];
                a[mi][3] = Xs[(r0 + g + 8) * NJ_LDA + k0 + tig + 4];
            }
            uint32_t b[2][2];
            #pragma unroll
            for (int ni = 0; ni < 2; ni++) {
                int c0 = np * 16 + ni * 8 + g;
                b[ni][0] = W1s[(k0 + tig) * NJ_LDB1 + c0];
                b[ni][1] = W1s[(k0 + tig + 4) * NJ_LDB1 + c0];
            }
            #pragma unroll
            for (int mi = 0; mi < 2; mi++)
                #pragma unroll
                for (int ni = 0; ni < 2; ni++)
                    mma_tf32(acc[mi][ni], a[mi][0], a[mi][1], a[mi][2], a[mi][3], b[ni][0], b[ni][1]);
        }
        #pragma unroll
        for (int mi = 0; mi < 2; mi++) {
            int r = mp * 32 + mi * 16 + g;
            #pragma unroll
            for (int ni = 0; ni < 2; ni++) {
                int cg = np * 16 + ni * 8 + 2 * tig;
                float bb0 = nb1[l * NH + cg], bb1 = nb1[l * NH + cg + 1];
                Hs[r * NJ_LDH + cg]           = f2tf(silu_f(acc[mi][ni][0] + bb0));
                Hs[r * NJ_LDH + cg + 1]       = f2tf(silu_f(acc[mi][ni][1] + bb1));
                Hs[(r + 8) * NJ_LDH + cg]     = f2tf(silu_f(acc[mi][ni][2] + bb0));
                Hs[(r + 8) * NJ_LDH + cg + 1] = f2tf(silu_f(acc[mi][ni][3] + bb1));
            }
        }
    }
    __syncthreads();

    // ---- GEMM2: [64x128] @ [128x112], 16 warps: mp=w&3 (16 rows), np=w>>2 (32 cols)
    {
        int mp = w & 3, np = w >> 2;
        float acc[4][4];
        #pragma unroll
        for (int j = 0; j < 4; j++)
            #pragma unroll
            for (int q = 0; q < 4; q++) acc[j][q] = 0.f;

        #pragma unroll 2
        for (int k0 = 0; k0 < 128; k0 += 8) {
            uint32_t a0 = Hs[(mp * 16 + g) * NJ_LDH + k0 + tig];
            uint32_t a1 = Hs[(mp * 16 + g + 8) * NJ_LDH + k0 + tig];
            uint32_t a2 = Hs[(mp * 16 + g) * NJ_LDH + k0 + tig + 4];
            uint32_t a3 = Hs[(mp * 16 + g + 8) * NJ_LDH + k0 + tig + 4];
            uint32_t b[4][2];
            #pragma unroll
            for (int j = 0; j < 4; j++) {
                int c0 = np * 32 + j * 8 + g;
                b[j][0] = W2s[(k0 + tig) * NJ_LDB2 + c0];
                b[j][1] = W2s[(k0 + tig + 4) * NJ_LDB2 + c0];
            }
            #pragma unroll
            for (int j = 0; j < 4; j++)
                mma_tf32(acc[j], a0, a1, a2, a3, b[j][0], b[j][1]);
        }

        #pragma unroll
        for (int j = 0; j < 4; j++) {
            int c = np * 32 + j * 8 + 2 * tig;
            if (c >= NF) continue;
            float bb0 = nb2[l * NF + c], bb1 = nb2[l * NF + c + 1];
            int r = m0 + mp * 16 + g;
            if (r < NN) {
                float2 f = *(float2*)&g_feats[(size_t)r * FP + c];
                f.x += acc[j][0] + bb0; f.y += acc[j][1] + bb1;
                *(float2*)&g_feats[(size_t)r * FP + c] = f;
            }
            if (r + 8 < NN) {
                float2 f = *(float2*)&g_feats[(size_t)(r + 8) * FP + c];
                f.x += acc[j][2] + bb0; f.y += acc[j][3] + bb1;
                *(float2*)&g_feats[(size_t)(r + 8) * FP + c] = f;
            }
        }
    }

    // re-zero g_mi for next layer
    for (int i = tid; i < 64 * MD; i += 512) {
        int n = m0 + i / MD;
        if (n < NN) g_mi[(size_t)n * MD + (i % MD)] = 0.f;
    }
}

// -------------------- global mean pool --------------------
__global__ void pool_kernel(const int* __restrict__ batch, float* __restrict__ out)
{
    __shared__ int s_lo, s_hi;
    __shared__ float red[256];
    int g = blockIdx.x, tid = threadIdx.x;
    if (tid == 0) { s_lo = lb_i(batch, NN, g); s_hi = lb_i(batch, NN, g + 1); }
    __syncthreads();
    float s = 0.f;
    if (tid < 2 * FP) {
        int part = tid / FP;
        int k = tid % FP;
        for (int n = s_lo + part; n < s_hi; n += 2)
            s += g_feats[(size_t)n * FP + k];
    }
    red[tid] = s;
    __syncthreads();
    if (tid < NF) {
        int c = s_hi - s_lo; if (c < 1) c = 1;
        out[g * NF + tid] = (red[tid] + red[tid + FP]) / (float)c;
    }
}

// -------------------- launch --------------------
extern "C" void kernel_launch(void* const* d_in, const int* in_sizes, int n_in,
                              void* d_out, int out_size)
{
    const float* x     = (const float*)d_in[0];
    const int*   ei    = (const int*)  d_in[1];
    const float* eattr = (const float*)d_in[2];
    const float* pos   = (const float*)d_in[3];
    const int*   batch = (const int*)  d_in[4];
    const float* emb[10];
    for (int i = 0; i < 10; i++) emb[i] = (const float*)d_in[5 + i];
    const float* ew1 = (const float*)d_in[15];
    const float* eb1 = (const float*)d_in[16];
    const float* ew2 = (const float*)d_in[17];
    const float* eb2 = (const float*)d_in[18];
    const float* nw1 = (const float*)d_in[19];
    const float* nb1 = (const float*)d_in[20];
    const float* nw2 = (const float*)d_in[21];
    const float* nb2 = (const float*)d_in[22];
    const float* lnw = (const float*)d_in[23];
    const float* lnb = (const float*)d_in[24];
    float* out = (float*)d_out;

    cudaFuncSetAttribute(precompP_kernel, cudaFuncAttributeMaxDynamicSharedMemorySize, PP_SMEM);
    cudaFuncSetAttribute(edge_kernel,     cudaFuncAttributeMaxDynamicSharedMemorySize, EDGE_SMEM);
    cudaFuncSetAttribute(node_kernel,     cudaFuncAttributeMaxDynamicSharedMemorySize, NJ_SMEM);

    embed_kernel<<<(NN * FP + 255) / 256, 256>>>(x, emb[0], emb[1], emb[2], emb[3],
                                                 emb[4], emb[5], emb[6], emb[7], emb[8], emb[9]);
    ea_kernel<<<(NE + 255) / 256, 256>>>(ei, eattr, pos);

    for (int l = 0; l < 2; l++) {
        precompP_kernel<<<dim3((NN + 63) / 64, 2), 256, PP_SMEM>>>(ew1, l);
        edge_kernel<<<E_GRID, 512, EDGE_SMEM>>>(ei, ew1, eb1, ew2, eb2, l);
        stats_partial_kernel<<<dim3(NG, 8), 256>>>(batch);
        stats_final_kernel<<<1, 64>>>(batch);
        node_kernel<<<(NN + 63) / 64, 512, NJ_SMEM>>>(batch, nw1, nb1, nw2, nb2, lnw, lnb, l);
    }
    pool_kernel<<<NG, 256>>>(batch, out);
}

// round 9
// speedup vs baseline: 1.8954x; 1.2798x over previous
#include <cuda_runtime.h>
#include <math.h>
#include <stdint.h>

#define NN   50000
#define NE   800000
#define NEL  850000
#define NG   64
#define FP   112
#define NF   110
#define MD   32
#define EH   128
#define NH   128
#define NIN  142
#define EFD  222

// -------- device scratch --------
__device__ float g_feats[NN * FP];
__device__ float g_P[(size_t)NN * 256];
__device__ float g_mi[NN * MD];
__device__ float g_ea[NE * 2];
__device__ float g_sum[NG], g_sum2[NG];
__device__ float g_mean[NG], g_rstd[NG];

// silu via HW tanh: x*sigmoid(x) = h*tanh(h) + h, h = x/2   (3 instrs, 1 MUFU)
__device__ __forceinline__ float silu_f(float x) {
    float h = 0.5f * x;
    float t;
    asm("tanh.approx.f32 %0, %1;" : "=f"(t) : "f"(h));
    return fmaf(h, t, h);
}
__device__ __forceinline__ uint32_t f2tf(float f) {
    uint32_t u; asm("cvt.rna.tf32.f32 %0, %1;" : "=r"(u) : "f"(f)); return u;
}
__device__ __forceinline__ void mma_tf32(float* d,
    uint32_t a0, uint32_t a1, uint32_t a2, uint32_t a3, uint32_t b0, uint32_t b1)
{
    asm volatile("mma.sync.aligned.m16n8k8.row.col.f32.tf32.tf32.f32 "
        "{%0,%1,%2,%3},{%4,%5,%6,%7},{%8,%9},{%0,%1,%2,%3};"
        : "+f"(d[0]), "+f"(d[1]), "+f"(d[2]), "+f"(d[3])
        : "r"(a0), "r"(a1), "r"(a2), "r"(a3), "r"(b0), "r"(b1));
}
__device__ __forceinline__ void ldsm_x4(uint32_t& r0, uint32_t& r1, uint32_t& r2, uint32_t& r3,
                                        uint32_t saddr)
{
    asm volatile("ldmatrix.sync.aligned.m8n8.x4.shared.b16 {%0,%1,%2,%3}, [%4];"
        : "=r"(r0), "=r"(r1), "=r"(r2), "=r"(r3) : "r"(saddr));
}
__device__ __forceinline__ int lb_i(const int* __restrict__ a, int n, int v) {
    int lo = 0, hi = n;
    while (lo < hi) { int m = (lo + hi) >> 1; if (a[m] < v) lo = m + 1; else hi = m; }
    return lo;
}

// -------------------- embed (+ zero g_mi) --------------------
__global__ void embed_kernel(const float* __restrict__ x,
    const float* __restrict__ e0, const float* __restrict__ e1,
    const float* __restrict__ e2, const float* __restrict__ e3,
    const float* __restrict__ e4, const float* __restrict__ e5,
    const float* __restrict__ e6, const float* __restrict__ e7,
    const float* __restrict__ e8, const float* __restrict__ e9)
{
    long idx = (long)blockIdx.x * blockDim.x + threadIdx.x;
    if (idx < (long)NN * MD) g_mi[idx] = 0.f;
    if (idx >= (long)NN * FP) return;
    int n = (int)(idx / FP), k = (int)(idx % FP);
    float v = 0.f;
    if (k < 6) {
        int keep = (k == 0) ? 0 : (10 + k);
        v = x[n * 16 + keep];
    } else if (k < 38) {
        int code = (int)x[n * 16 + 1];
        v = e0[code * 32 + (k - 6)];
    } else if (k < 110) {
        int t = (k - 38) >> 3, c = (k - 38) & 7;
        int code = (int)x[n * 16 + 2 + t];
        const float* es[9] = {e1, e2, e3, e4, e5, e6, e7, e8, e9};
        v = es[t][code * 8 + c];
    }
    g_feats[idx] = v;
}

// -------------------- edge attr + rel dist --------------------
__global__ void ea_kernel(const int* __restrict__ ei,
                          const float* __restrict__ eattr,
                          const float* __restrict__ pos)
{
    int e = blockIdx.x * blockDim.x + threadIdx.x;
    if (e >= NE) return;
    int s = ei[e], d = ei[NE + e];
    float dx = pos[s * 3 + 0] - pos[d * 3 + 0];
    float dy = pos[s * 3 + 1] - pos[d * 3 + 1];
    float dz = pos[s * 3 + 2] - pos[d * 3 + 2];
    g_ea[2 * e + 0] = eattr[e];
    g_ea[2 * e + 1] = dx * dx + dy * dy + dz * dz;
}

// ==================== persistent precompP: [64x112] @ [112x128] per half ====================
#define PP_LDA 116
#define PP_LDB 136
#define PP_TILES ((NN + 63) / 64)
#define PP_SMEM ((64 * PP_LDA + 112 * PP_LDB) * 4)
__global__ void precompP_kernel(const float* __restrict__ w1, int l)
{
    extern __shared__ float sm[];
    uint32_t* Xs = (uint32_t*)sm;
    uint32_t* Ws = Xs + 64 * PP_LDA;
    int tid = threadIdx.x;
    int half = blockIdx.y;

    if (blockIdx.x == 0 && half == 0 && tid < 2 * NG) {
        if (tid < NG) g_sum[tid] = 0.f; else g_sum2[tid - NG] = 0.f;
    }

    // weights resident for whole kernel
    const float* wbase = w1 + (size_t)l * EFD * EH + (size_t)half * 110 * EH;
    for (int i = tid; i < 112 * PP_LDB; i += 256) {
        int k = i / PP_LDB, c = i % PP_LDB;
        Ws[i] = (k < 110 && c < 128) ? f2tf(wbase[(size_t)k * EH + c]) : 0u;
    }

    int w = tid >> 5, lane = tid & 31;
    int g = lane >> 2, tig = lane & 3;
    int mp = w & 1;
    int ng = w >> 1;

    for (int tile = blockIdx.x; tile < PP_TILES; tile += 148) {
        int m0 = tile * 64;
        __syncthreads();     // protects Xs reuse; also covers first-iter W load
        for (int i = tid; i < 64 * PP_LDA; i += 256) {
            int r = i / PP_LDA, c = i % PP_LDA;
            int n = m0 + r;
            Xs[i] = (n < NN && c < FP) ? f2tf(g_feats[(size_t)n * FP + c]) : 0u;
        }
        __syncthreads();

        float acc[2][4][4];
        #pragma unroll
        for (int mi = 0; mi < 2; mi++)
            #pragma unroll
            for (int j = 0; j < 4; j++)
                #pragma unroll
                for (int q = 0; q < 4; q++) acc[mi][j][q] = 0.f;

        #pragma unroll 2
        for (int k0 = 0; k0 < 112; k0 += 8) {
            uint32_t a[2][4];
            #pragma unroll
            for (int mi = 0; mi < 2; mi++) {
                int r0 = mp * 32 + mi * 16;
                a[mi][0] = Xs[(r0 + g) * PP_LDA + k0 + tig];
                a[mi][1] = Xs[(r0 + g + 8) * PP_LDA + k0 + tig];
                a[mi][2] = Xs[(r0 + g) * PP_LDA + k0 + tig + 4];
                a[mi][3] = Xs[(r0 + g + 8) * PP_LDA + k0 + tig + 4];
            }
            uint32_t b[4][2];
            #pragma unroll
            for (int j = 0; j < 4; j++) {
                int c0 = ng * 32 + j * 8 + g;
                b[j][0] = Ws[(k0 + tig) * PP_LDB + c0];
                b[j][1] = Ws[(k0 + tig + 4) * PP_LDB + c0];
            }
            #pragma unroll
            for (int mi = 0; mi < 2; mi++)
                #pragma unroll
                for (int j = 0; j < 4; j++)
                    mma_tf32(acc[mi][j], a[mi][0], a[mi][1], a[mi][2], a[mi][3], b[j][0], b[j][1]);
        }

        #pragma unroll
        for (int mi = 0; mi < 2; mi++) {
            int r = m0 + mp * 32 + mi * 16 + g;
            #pragma unroll
            for (int j = 0; j < 4; j++) {
                int col = half * 128 + ng * 32 + j * 8 + 2 * tig;
                if (r < NN)
                    *(float2*)&g_P[(size_t)r * 256 + col] = make_float2(acc[mi][j][0], acc[mi][j][1]);
                if (r + 8 < NN)
                    *(float2*)&g_P[(size_t)(r + 8) * 256 + col] = make_float2(acc[mi][j][2], acc[mi][j][3]);
            }
        }
    }
}

// ==================== persistent edge (512 thr): gather + tf32 MMA (ldmatrix) + scatter ====================
#define E_LDA 132
#define E_LDM 36
#define E_NT  ((NEL + 127) / 128)
#define E_GRID 296
#define EDGE_SMEM ((128 * E_LDA + 32 * E_LDA + 32 + 128 * 4) * 4)
__global__ void __launch_bounds__(512, 2) edge_kernel(const int* __restrict__ ei,
    const float* __restrict__ w1, const float* __restrict__ b1,
    const float* __restrict__ w2, const float* __restrict__ b2, int l)
{
    extern __shared__ float sm[];
    float* Hs  = sm;                        // 128 x 132 (tf32 bits); reused as Ms 128 x 36
    float* WTs = Hs + 128 * E_LDA;          // 32(c) x 132(k) transposed W2 (tf32 bits)
    float* b2s = WTs + 32 * E_LDA;
    int4*  eds = (int4*)(b2s + 32);         // (src, dst, ea_bits, dist_bits) per edge
    uint32_t* HsU = (uint32_t*)Hs;
    float* Ms = Hs;

    int tid = threadIdx.x;
    const float* w1b = w1 + (size_t)l * EFD * EH;

    // per-thread loop-invariant phase-1 constants (k0 fixed per thread)
    int k0 = (tid & 31) * 4;
    float4 cw0 = *(const float4*)&w1b[220 * EH + k0];
    float4 cw1 = *(const float4*)&w1b[221 * EH + k0];
    float4 cb1 = *(const float4*)&b1[l * EH + k0];

    if (tid < 32) b2s[tid] = b2[l * MD + tid];
    for (int i = tid; i < 128 * 32; i += 512) {
        int k = i >> 5, c = i & 31;
        WTs[c * E_LDA + k] = __uint_as_float(f2tf(w2[(size_t)l * EH * MD + i]));
    }

    int wid = tid >> 5, lane = tid & 31;   // 16 warps
    int g = lane >> 2, tig = lane & 3;
    int mp = wid & 7;          // 16-row strip
    int np = wid >> 3;         // 16-col strip

    uint32_t HsS = (uint32_t)__cvta_generic_to_shared(Hs);
    uint32_t WTS = (uint32_t)__cvta_generic_to_shared(WTs);
    int lrow = ((lane >> 3) & 1) * 8 + (lane & 7);
    int lcol = (lane >> 4) * 4;
    uint32_t aBase = HsS + (uint32_t)(((mp * 16 + lrow) * E_LDA + lcol) * 4);
    uint32_t bBase = WTS + (uint32_t)(((np * 16 + lrow) * E_LDA + lcol) * 4);

    for (int tile = blockIdx.x; tile < E_NT; tile += E_GRID) {
        int e0 = tile * 128;
        __syncthreads();
        if (tid < 128) {
            int e = e0 + tid;
            int s = -1, d = -1; float a = 0.f, dd = 0.f;
            if (e < NEL) {
                if (e < NE) { s = ei[e]; d = ei[NE + e]; a = g_ea[2 * e]; dd = g_ea[2 * e + 1]; }
                else        { s = d = e - NE; }
            }
            eds[tid] = make_int4(s, d, __float_as_int(a), __float_as_int(dd));
        }
        __syncthreads();

        // phase 1: H = silu(Pd[dst] + Ps[src] + ea*w220 + dist*w221 + b1)
        #pragma unroll
        for (int it = 0; it < 8; ++it) {
            int e = it * 16 + wid;
            int4 ed = eds[e];
            uint4 u = make_uint4(0u, 0u, 0u, 0u);
            if (ed.y >= 0) {
                float4 pd = *(const float4*)(g_P + (ed.y * 256 + k0));
                float4 ps = *(const float4*)(g_P + (ed.x * 256 + 128 + k0));
                float a = __int_as_float(ed.z), dd = __int_as_float(ed.w);
                u.x = f2tf(silu_f(pd.x + ps.x + a * cw0.x + dd * cw1.x + cb1.x));
                u.y = f2tf(silu_f(pd.y + ps.y + a * cw0.y + dd * cw1.y + cb1.y));
                u.z = f2tf(silu_f(pd.z + ps.z + a * cw0.z + dd * cw1.z + cb1.z));
                u.w = f2tf(silu_f(pd.w + ps.w + a * cw0.w + dd * cw1.w + cb1.w));
            }
            *(uint4*)&HsU[e * E_LDA + k0] = u;
        }
        __syncthreads();

        // phase 2: [128x128] @ [128x32] tf32 MMA via ldmatrix
        float acc[2][4];
        #pragma unroll
        for (int ni = 0; ni < 2; ni++)
            #pragma unroll
            for (int q = 0; q < 4; q++) acc[ni][q] = 0.f;

        #pragma unroll 4
        for (int ks = 0; ks < 16; ++ks) {
            uint32_t a0, a1, a2, a3, b00, b10, b01, b11;
            ldsm_x4(a0, a1, a2, a3, aBase + ks * 32);
            ldsm_x4(b00, b10, b01, b11, bBase + ks * 32);
            mma_tf32(acc[0], a0, a1, a2, a3, b00, b01);
            mma_tf32(acc[1], a0, a1, a2, a3, b10, b11);
        }
        __syncthreads();

        {
            int r = mp * 16 + g;
            #pragma unroll
            for (int ni = 0; ni < 2; ni++) {
                int c = np * 16 + ni * 8 + 2 * tig;
                Ms[r * E_LDM + c]           = silu_f(acc[ni][0] + b2s[c]);
                Ms[r * E_LDM + c + 1]       = silu_f(acc[ni][1] + b2s[c + 1]);
                Ms[(r + 8) * E_LDM + c]     = silu_f(acc[ni][2] + b2s[c]);
                Ms[(r + 8) * E_LDM + c + 1] = silu_f(acc[ni][3] + b2s[c + 1]);
            }
        }
        __syncthreads();

        // scatter: 4 threads per edge, 2 float4 RED each
        int e = tid >> 2;
        int cb = (tid & 3) * 8;
        int d = eds[e].y;
        if (d >= 0) {
            float4 v0 = *(const float4*)&Ms[e * E_LDM + cb];
            float4 v1 = *(const float4*)&Ms[e * E_LDM + cb + 4];
            atomicAdd((float4*)(g_mi + (d * MD + cb)), v0);
            atomicAdd((float4*)(g_mi + (d * MD + cb + 4)), v1);
        }
    }
}

// -------------------- LN stats --------------------
__global__ void stats_partial_kernel(const int* __restrict__ batch)
{
    __shared__ int s_lo, s_hi;
    __shared__ float rs[8], rs2[8];
    int g = blockIdx.x, part = blockIdx.y;
    int tid = threadIdx.x;
    if (tid == 0) { s_lo = lb_i(batch, NN, g); s_hi = lb_i(batch, NN, g + 1); }
    __syncthreads();
    int total = (s_hi - s_lo) * FP;
    int chunk = (total + 7) >> 3;
    int st = part * chunk;
    int en = st + chunk; if (en > total) en = total;
    const float* base = g_feats + (size_t)s_lo * FP;
    float s = 0.f, s2 = 0.f;
    for (int i = st + tid; i < en; i += 256) { float v = base[i]; s += v; s2 += v * v; }
    #pragma unroll
    for (int o = 16; o; o >>= 1) {
        s  += __shfl_down_sync(0xffffffffu, s, o);
        s2 += __shfl_down_sync(0xffffffffu, s2, o);
    }
    if ((tid & 31) == 0) { rs[tid >> 5] = s; rs2[tid >> 5] = s2; }
    __syncthreads();
    if (tid == 0) {
        float a = 0.f, b = 0.f;
        for (int i = 0; i < 8; i++) { a += rs[i]; b += rs2[i]; }
        atomicAdd(&g_sum[g], a); atomicAdd(&g_sum2[g], b);
    }
}

__global__ void stats_final_kernel(const int* __restrict__ batch)
{
    int g = threadIdx.x;
    if (g >= NG) return;
    int lo = lb_i(batch, NN, g), hi = lb_i(batch, NN, g + 1);
    int c = hi - lo; if (c < 1) c = 1;
    float denom = (float)c * 110.f;
    float mean = g_sum[g] / denom;
    float var = g_sum2[g] / denom - mean * mean;
    var = fmaxf(var, 0.f);
    g_mean[g] = mean;
    g_rstd[g] = rsqrtf(var + 1e-5f);
}

// ==================== persistent fused node MLP (512 thr, weights resident) ====================
#define NJ_LDA 148
#define NJ_LDB1 136
#define NJ_LDH 132
#define NJ_LDB2 136
#define NJ_TILES ((NN + 63) / 64)
#define NJ_GRID 296
#define NJ_SMEM ((64 * NJ_LDA + 144 * NJ_LDB1 + 64 * NJ_LDH + 128 * NJ_LDB2) * 4)
__global__ void __launch_bounds__(512) node_kernel(const int* __restrict__ batch,
    const float* __restrict__ nw1, const float* __restrict__ nb1,
    const float* __restrict__ nw2, const float* __restrict__ nb2,
    const float* __restrict__ lnw, const float* __restrict__ lnb, int l)
{
    extern __shared__ float sm[];
    uint32_t* Xs  = (uint32_t*)sm;                  // 64 x 148
    uint32_t* W1s = Xs + 64 * NJ_LDA;               // 144 x 136
    uint32_t* Hs  = W1s + 144 * NJ_LDB1;            // 64 x 132
    uint32_t* W2s = Hs + 64 * NJ_LDH;               // 128 x 136
    int tid = threadIdx.x;

    // weights resident for whole kernel
    const float* w1b = nw1 + (size_t)l * NIN * NH;
    for (int i = tid; i < 144 * NJ_LDB1; i += 512) {
        int k = i / NJ_LDB1, c = i % NJ_LDB1;
        W1s[i] = (k < NIN && c < NH) ? f2tf(w1b[(size_t)k * NH + c]) : 0u;
    }
    const float* w2b = nw2 + (size_t)l * NH * NF;
    for (int i = tid; i < 128 * NJ_LDB2; i += 512) {
        int k = i / NJ_LDB2, c = i % NJ_LDB2;
        W2s[i] = (c < NF) ? f2tf(w2b[(size_t)k * NF + c]) : 0u;
    }

    int w = tid >> 5, lane = tid & 31;
    int g = lane >> 2, tig = lane & 3;

    for (int tile = blockIdx.x; tile < NJ_TILES; tile += NJ_GRID) {
        int m0 = tile * 64;
        __syncthreads();    // protects Xs/Hs reuse; covers first-iter W load
        for (int i = tid; i < 64 * NJ_LDA; i += 512) {
            int n = m0 + i / NJ_LDA, k = i % NJ_LDA;
            float v = 0.f;
            if (n < NN) {
                if (k < NF) {
                    int gg = batch[n];
                    float f = g_feats[(size_t)n * FP + k];
                    v = lnw[l * NF + k] * ((f - g_mean[gg]) * g_rstd[gg]) + lnb[l * NF + k];
                } else if (k < NIN) {
                    v = g_mi[(size_t)n * MD + (k - NF)];
                }
            }
            Xs[i] = f2tf(v);
        }
        __syncthreads();

        // ---- GEMM1: [64x144] @ [144x128]
        {
            int mp = w & 1, np = w >> 1;
            float acc[2][2][4];
            #pragma unroll
            for (int mi = 0; mi < 2; mi++)
                #pragma unroll
                for (int ni = 0; ni < 2; ni++)
                    #pragma unroll
                    for (int q = 0; q < 4; q++) acc[mi][ni][q] = 0.f;

            #pragma unroll 2
            for (int k0 = 0; k0 < 144; k0 += 8) {
                uint32_t a[2][4];
                #pragma unroll
                for (int mi = 0; mi < 2; mi++) {
                    int r0 = mp * 32 + mi * 16;
                    a[mi][0] = Xs[(r0 + g) * NJ_LDA + k0 + tig];
                    a[mi][1] = Xs[(r0 + g + 8) * NJ_LDA + k0 + tig];
                    a[mi][2] = Xs[(r0 + g) * NJ_LDA + k0 + tig + 4];
                    a[mi][3] = Xs[(r0 + g + 8) * NJ_LDA + k0 + tig + 4];
                }
                uint32_t b[2][2];
                #pragma unroll
                for (int ni = 0; ni < 2; ni++) {
                    int c0 = np * 16 + ni * 8 + g;
                    b[ni][0] = W1s[(k0 + tig) * NJ_LDB1 + c0];
                    b[ni][1] = W1s[(k0 + tig + 4) * NJ_LDB1 + c0];
                }
                #pragma unroll
                for (int mi = 0; mi < 2; mi++)
                    #pragma unroll
                    for (int ni = 0; ni < 2; ni++)
                        mma_tf32(acc[mi][ni], a[mi][0], a[mi][1], a[mi][2], a[mi][3], b[ni][0], b[ni][1]);
            }
            #pragma unroll
            for (int mi = 0; mi < 2; mi++) {
                int r = mp * 32 + mi * 16 + g;
                #pragma unroll
                for (int ni = 0; ni < 2; ni++) {
                    int cg = np * 16 + ni * 8 + 2 * tig;
                    float bb0 = nb1[l * NH + cg], bb1 = nb1[l * NH + cg + 1];
                    Hs[r * NJ_LDH + cg]           = f2tf(silu_f(acc[mi][ni][0] + bb0));
                    Hs[r * NJ_LDH + cg + 1]       = f2tf(silu_f(acc[mi][ni][1] + bb1));
                    Hs[(r + 8) * NJ_LDH + cg]     = f2tf(silu_f(acc[mi][ni][2] + bb0));
                    Hs[(r + 8) * NJ_LDH + cg + 1] = f2tf(silu_f(acc[mi][ni][3] + bb1));
                }
            }
        }
        __syncthreads();

        // ---- GEMM2: [64x128] @ [128x112]
        {
            int mp = w & 3, np = w >> 2;
            float acc[4][4];
            #pragma unroll
            for (int j = 0; j < 4; j++)
                #pragma unroll
                for (int q = 0; q < 4; q++) acc[j][q] = 0.f;

            #pragma unroll 2
            for (int k0 = 0; k0 < 128; k0 += 8) {
                uint32_t a0 = Hs[(mp * 16 + g) * NJ_LDH + k0 + tig];
                uint32_t a1 = Hs[(mp * 16 + g + 8) * NJ_LDH + k0 + tig];
                uint32_t a2 = Hs[(mp * 16 + g) * NJ_LDH + k0 + tig + 4];
                uint32_t a3 = Hs[(mp * 16 + g + 8) * NJ_LDH + k0 + tig + 4];
                uint32_t b[4][2];
                #pragma unroll
                for (int j = 0; j < 4; j++) {
                    int c0 = np * 32 + j * 8 + g;
                    b[j][0] = W2s[(k0 + tig) * NJ_LDB2 + c0];
                    b[j][1] = W2s[(k0 + tig + 4) * NJ_LDB2 + c0];
                }
                #pragma unroll
                for (int j = 0; j < 4; j++)
                    mma_tf32(acc[j], a0, a1, a2, a3, b[j][0], b[j][1]);
            }

            #pragma unroll
            for (int j = 0; j < 4; j++) {
                int c = np * 32 + j * 8 + 2 * tig;
                if (c >= NF) continue;
                float bb0 = nb2[l * NF + c], bb1 = nb2[l * NF + c + 1];
                int r = m0 + mp * 16 + g;
                if (r < NN) {
                    float2 f = *(float2*)&g_feats[(size_t)r * FP + c];
                    f.x += acc[j][0] + bb0; f.y += acc[j][1] + bb1;
                    *(float2*)&g_feats[(size_t)r * FP + c] = f;
                }
                if (r + 8 < NN) {
                    float2 f = *(float2*)&g_feats[(size_t)(r + 8) * FP + c];
                    f.x += acc[j][2] + bb0; f.y += acc[j][3] + bb1;
                    *(float2*)&g_feats[(size_t)(r + 8) * FP + c] = f;
                }
            }
        }

        // re-zero g_mi for next layer
        for (int i = tid; i < 64 * MD; i += 512) {
            int n = m0 + i / MD;
            if (n < NN) g_mi[(size_t)n * MD + (i % MD)] = 0.f;
        }
    }
}

// -------------------- global mean pool --------------------
__global__ void pool_kernel(const int* __restrict__ batch, float* __restrict__ out)
{
    __shared__ int s_lo, s_hi;
    __shared__ float red[256];
    int g = blockIdx.x, tid = threadIdx.x;
    if (tid == 0) { s_lo = lb_i(batch, NN, g); s_hi = lb_i(batch, NN, g + 1); }
    __syncthreads();
    float s = 0.f;
    if (tid < 2 * FP) {
        int part = tid / FP;
        int k = tid % FP;
        for (int n = s_lo + part; n < s_hi; n += 2)
            s += g_feats[(size_t)n * FP + k];
    }
    red[tid] = s;
    __syncthreads();
    if (tid < NF) {
        int c = s_hi - s_lo; if (c < 1) c = 1;
        out[g * NF + tid] = (red[tid] + red[tid + FP]) / (float)c;
    }
}

// -------------------- launch --------------------
extern "C" void kernel_launch(void* const* d_in, const int* in_sizes, int n_in,
                              void* d_out, int out_size)
{
    const float* x     = (const float*)d_in[0];
    const int*   ei    = (const int*)  d_in[1];
    const float* eattr = (const float*)d_in[2];
    const float* pos   = (const float*)d_in[3];
    const int*   batch = (const int*)  d_in[4];
    const float* emb[10];
    for (int i = 0; i < 10; i++) emb[i] = (const float*)d_in[5 + i];
    const float* ew1 = (const float*)d_in[15];
    const float* eb1 = (const float*)d_in[16];
    const float* ew2 = (const float*)d_in[17];
    const float* eb2 = (const float*)d_in[18];
    const float* nw1 = (const float*)d_in[19];
    const float* nb1 = (const float*)d_in[20];
    const float* nw2 = (const float*)d_in[21];
    const float* nb2 = (const float*)d_in[22];
    const float* lnw = (const float*)d_in[23];
    const float* lnb = (const float*)d_in[24];
    float* out = (float*)d_out;

    cudaFuncSetAttribute(precompP_kernel, cudaFuncAttributeMaxDynamicSharedMemorySize, PP_SMEM);
    cudaFuncSetAttribute(edge_kernel,     cudaFuncAttributeMaxDynamicSharedMemorySize, EDGE_SMEM);
    cudaFuncSetAttribute(node_kernel,     cudaFuncAttributeMaxDynamicSharedMemorySize, NJ_SMEM);

    embed_kernel<<<(NN * FP + 255) / 256, 256>>>(x, emb[0], emb[1], emb[2], emb[3],
                                                 emb[4], emb[5], emb[6], emb[7], emb[8], emb[9]);
    ea_kernel<<<(NE + 255) / 256, 256>>>(ei, eattr, pos);

    for (int l = 0; l < 2; l++) {
        precompP_kernel<<<dim3(148, 2), 256, PP_SMEM>>>(ew1, l);
        edge_kernel<<<E_GRID, 512, EDGE_SMEM>>>(ei, ew1, eb1, ew2, eb2, l);
        stats_partial_kernel<<<dim3(NG, 8), 256>>>(batch);
        stats_final_kernel<<<1, 64>>>(batch);
        node_kernel<<<NJ_GRID, 512, NJ_SMEM>>>(batch, nw1, nb1, nw2, nb2, lnw, lnb, l);
    }
    pool_kernel<<<NG, 256>>>(batch, out);
}

// round 10
// speedup vs baseline: 1.9967x; 1.0534x over previous
#include <cuda_runtime.h>
#include <cuda_fp16.h>
#include <math.h>
#include <stdint.h>

#define NN   50000
#define NE   800000
#define NEL  850000
#define NG   64
#define FP   112
#define NF   110
#define MD   32
#define EH   128
#define NH   128
#define NIN  142
#define EFD  222

// -------- device scratch --------
__device__ float  g_feats[NN * FP];
__device__ __half g_P[(size_t)NN * 256];      // fp16 (same mantissa as tf32)
__device__ float  g_mi[NN * MD];
__device__ float  g_ea[NE * 2];
__device__ float  g_sum[NG], g_sum2[NG];
__device__ float  g_mean[NG], g_rstd[NG];

// silu via HW tanh: x*sigmoid(x) = h*tanh(h) + h, h = x/2
__device__ __forceinline__ float silu_f(float x) {
    float h = 0.5f * x;
    float t;
    asm("tanh.approx.f32 %0, %1;" : "=f"(t) : "f"(h));
    return fmaf(h, t, h);
}
__device__ __forceinline__ uint32_t f2tf(float f) {
    uint32_t u; asm("cvt.rna.tf32.f32 %0, %1;" : "=r"(u) : "f"(f)); return u;
}
__device__ __forceinline__ void mma_tf32(float* d,
    uint32_t a0, uint32_t a1, uint32_t a2, uint32_t a3, uint32_t b0, uint32_t b1)
{
    asm volatile("mma.sync.aligned.m16n8k8.row.col.f32.tf32.tf32.f32 "
        "{%0,%1,%2,%3},{%4,%5,%6,%7},{%8,%9},{%0,%1,%2,%3};"
        : "+f"(d[0]), "+f"(d[1]), "+f"(d[2]), "+f"(d[3])
        : "r"(a0), "r"(a1), "r"(a2), "r"(a3), "r"(b0), "r"(b1));
}
__device__ __forceinline__ void ldsm_x4(uint32_t& r0, uint32_t& r1, uint32_t& r2, uint32_t& r3,
                                        uint32_t saddr)
{
    asm volatile("ldmatrix.sync.aligned.m8n8.x4.shared.b16 {%0,%1,%2,%3}, [%4];"
        : "=r"(r0), "=r"(r1), "=r"(r2), "=r"(r3) : "r"(saddr));
}
__device__ __forceinline__ int lb_i(const int* __restrict__ a, int n, int v) {
    int lo = 0, hi = n;
    while (lo < hi) { int m = (lo + hi) >> 1; if (a[m] < v) lo = m + 1; else hi = m; }
    return lo;
}

// -------------------- embed (+ zero g_mi) --------------------
__global__ void embed_kernel(const float* __restrict__ x,
    const float* __restrict__ e0, const float* __restrict__ e1,
    const float* __restrict__ e2, const float* __restrict__ e3,
    const float* __restrict__ e4, const float* __restrict__ e5,
    const float* __restrict__ e6, const float* __restrict__ e7,
    const float* __restrict__ e8, const float* __restrict__ e9)
{
    long idx = (long)blockIdx.x * blockDim.x + threadIdx.x;
    if (idx < (long)NN * MD) g_mi[idx] = 0.f;
    if (idx >= (long)NN * FP) return;
    int n = (int)(idx / FP), k = (int)(idx % FP);
    float v = 0.f;
    if (k < 6) {
        int keep = (k == 0) ? 0 : (10 + k);
        v = x[n * 16 + keep];
    } else if (k < 38) {
        int code = (int)x[n * 16 + 1];
        v = e0[code * 32 + (k - 6)];
    } else if (k < 110) {
        int t = (k - 38) >> 3, c = (k - 38) & 7;
        int code = (int)x[n * 16 + 2 + t];
        const float* es[9] = {e1, e2, e3, e4, e5, e6, e7, e8, e9};
        v = es[t][code * 8 + c];
    }
    g_feats[idx] = v;
}

// -------------------- edge attr + rel dist --------------------
__global__ void ea_kernel(const int* __restrict__ ei,
                          const float* __restrict__ eattr,
                          const float* __restrict__ pos)
{
    int e = blockIdx.x * blockDim.x + threadIdx.x;
    if (e >= NE) return;
    int s = ei[e], d = ei[NE + e];
    float dx = pos[s * 3 + 0] - pos[d * 3 + 0];
    float dy = pos[s * 3 + 1] - pos[d * 3 + 1];
    float dz = pos[s * 3 + 2] - pos[d * 3 + 2];
    g_ea[2 * e + 0] = eattr[e];
    g_ea[2 * e + 1] = dx * dx + dy * dy + dz * dz;
}

// ==================== persistent precompP (512 thr, both halves resident) ====================
// P[n][0:128] = feats @ W1[0:110], P[n][128:256] = feats @ W1[110:220]  (fp16 out)
#define PP_LDA 116
#define PP_LDB 264
#define PP_TILES ((NN + 63) / 64)
#define PP_SMEM ((64 * PP_LDA + 112 * PP_LDB) * 4)
__global__ void __launch_bounds__(512) precompP_kernel(const float* __restrict__ w1, int l)
{
    extern __shared__ float sm[];
    uint32_t* Xs = (uint32_t*)sm;              // 64 x 116
    uint32_t* Ws = Xs + 64 * PP_LDA;           // 112 x 264 (256 out-cols + pad; rows>=110 zero)
    int tid = threadIdx.x;

    if (blockIdx.x == 0 && tid < 2 * NG) {
        if (tid < NG) g_sum[tid] = 0.f; else g_sum2[tid - NG] = 0.f;
    }

    const float* w1b = w1 + (size_t)l * EFD * EH;
    for (int i = tid; i < 112 * PP_LDB; i += 512) {
        int k = i / PP_LDB, c = i % PP_LDB;
        uint32_t v = 0u;
        if (k < 110 && c < 256) {
            const float* base = w1b + (c < 128 ? 0 : 110 * EH);
            v = f2tf(base[(size_t)k * EH + (c & 127)]);
        }
        Ws[i] = v;
    }

    int w = tid >> 5, lane = tid & 31;
    int g = lane >> 2, tig = lane & 3;
    int mp = w & 1;          // 2 strips of 32 rows
    int ng = w >> 1;         // 8 strips of 32 cols over 256

    for (int tile = blockIdx.x; tile < PP_TILES; tile += 148) {
        int m0 = tile * 64;
        __syncthreads();     // protects Xs reuse; covers first-iter W load
        for (int i = tid; i < 64 * PP_LDA; i += 512) {
            int r = i / PP_LDA, c = i % PP_LDA;
            int n = m0 + r;
            Xs[i] = (n < NN && c < FP) ? f2tf(g_feats[(size_t)n * FP + c]) : 0u;
        }
        __syncthreads();

        float acc[2][4][4];
        #pragma unroll
        for (int mi = 0; mi < 2; mi++)
            #pragma unroll
            for (int j = 0; j < 4; j++)
                #pragma unroll
                for (int q = 0; q < 4; q++) acc[mi][j][q] = 0.f;

        #pragma unroll 2
        for (int k0 = 0; k0 < 112; k0 += 8) {
            uint32_t a[2][4];
            #pragma unroll
            for (int mi = 0; mi < 2; mi++) {
                int r0 = mp * 32 + mi * 16;
                a[mi][0] = Xs[(r0 + g) * PP_LDA + k0 + tig];
                a[mi][1] = Xs[(r0 + g + 8) * PP_LDA + k0 + tig];
                a[mi][2] = Xs[(r0 + g) * PP_LDA + k0 + tig + 4];
                a[mi][3] = Xs[(r0 + g + 8) * PP_LDA + k0 + tig + 4];
            }
            uint32_t b[4][2];
            #pragma unroll
            for (int j = 0; j < 4; j++) {
                int c0 = ng * 32 + j * 8 + g;
                b[j][0] = Ws[(k0 + tig) * PP_LDB + c0];
                b[j][1] = Ws[(k0 + tig + 4) * PP_LDB + c0];
            }
            #pragma unroll
            for (int mi = 0; mi < 2; mi++)
                #pragma unroll
                for (int j = 0; j < 4; j++)
                    mma_tf32(acc[mi][j], a[mi][0], a[mi][1], a[mi][2], a[mi][3], b[j][0], b[j][1]);
        }

        #pragma unroll
        for (int mi = 0; mi < 2; mi++) {
            int r = m0 + mp * 32 + mi * 16 + g;
            #pragma unroll
            for (int j = 0; j < 4; j++) {
                int col = ng * 32 + j * 8 + 2 * tig;
                if (r < NN)
                    *(__half2*)&g_P[(size_t)r * 256 + col] =
                        __float22half2_rn(make_float2(acc[mi][j][0], acc[mi][j][1]));
                if (r + 8 < NN)
                    *(__half2*)&g_P[(size_t)(r + 8) * 256 + col] =
                        __float22half2_rn(make_float2(acc[mi][j][2], acc[mi][j][3]));
            }
        }
    }
}

// ==================== persistent edge (512 thr): fp16 gather + tf32 MMA + scatter ====================
#define E_LDA 132
#define E_LDM 36
#define E_NT  ((NEL + 127) / 128)
#define E_GRID 296
#define EDGE_SMEM ((128 * E_LDA + 32 * E_LDA + 32 + 128 * 4) * 4)
__global__ void __launch_bounds__(512, 2) edge_kernel(const int* __restrict__ ei,
    const float* __restrict__ w1, const float* __restrict__ b1,
    const float* __restrict__ w2, const float* __restrict__ b2, int l)
{
    extern __shared__ float sm[];
    float* Hs  = sm;                        // 128 x 132 (tf32 bits); reused as Ms 128 x 36
    float* WTs = Hs + 128 * E_LDA;          // 32(c) x 132(k) transposed W2 (tf32 bits)
    float* b2s = WTs + 32 * E_LDA;
    int4*  eds = (int4*)(b2s + 32);
    uint32_t* HsU = (uint32_t*)Hs;
    float* Ms = Hs;

    int tid = threadIdx.x;
    const float* w1b = w1 + (size_t)l * EFD * EH;

    int k0 = (tid & 31) * 4;
    float4 cw0 = *(const float4*)&w1b[220 * EH + k0];
    float4 cw1 = *(const float4*)&w1b[221 * EH + k0];
    float4 cb1 = *(const float4*)&b1[l * EH + k0];

    if (tid < 32) b2s[tid] = b2[l * MD + tid];
    for (int i = tid; i < 128 * 32; i += 512) {
        int k = i >> 5, c = i & 31;
        WTs[c * E_LDA + k] = __uint_as_float(f2tf(w2[(size_t)l * EH * MD + i]));
    }

    int wid = tid >> 5, lane = tid & 31;
    int g = lane >> 2, tig = lane & 3;
    int mp = wid & 7;
    int np = wid >> 3;

    uint32_t HsS = (uint32_t)__cvta_generic_to_shared(Hs);
    uint32_t WTS = (uint32_t)__cvta_generic_to_shared(WTs);
    int lrow = ((lane >> 3) & 1) * 8 + (lane & 7);
    int lcol = (lane >> 4) * 4;
    uint32_t aBase = HsS + (uint32_t)(((mp * 16 + lrow) * E_LDA + lcol) * 4);
    uint32_t bBase = WTS + (uint32_t)(((np * 16 + lrow) * E_LDA + lcol) * 4);

    for (int tile = blockIdx.x; tile < E_NT; tile += E_GRID) {
        int e0 = tile * 128;
        __syncthreads();
        if (tid < 128) {
            int e = e0 + tid;
            int s = -1, d = -1; float a = 0.f, dd = 0.f;
            if (e < NEL) {
                if (e < NE) { s = ei[e]; d = ei[NE + e]; a = g_ea[2 * e]; dd = g_ea[2 * e + 1]; }
                else        { s = d = e - NE; }
            }
            eds[tid] = make_int4(s, d, __float_as_int(a), __float_as_int(dd));
        }
        __syncthreads();

        // phase 1: H = silu(Pd[dst] + Ps[src] + ea*w220 + dist*w221 + b1), fp16 gather
        #pragma unroll
        for (int it = 0; it < 8; ++it) {
            int e = it * 16 + wid;
            int4 ed = eds[e];
            uint4 u = make_uint4(0u, 0u, 0u, 0u);
            if (ed.y >= 0) {
                uint2 pdu = *(const uint2*)(g_P + (ed.y * 256 + k0));
                uint2 psu = *(const uint2*)(g_P + (ed.x * 256 + 128 + k0));
                float2 pd01 = __half22float2(*reinterpret_cast<__half2*>(&pdu.x));
                float2 pd23 = __half22float2(*reinterpret_cast<__half2*>(&pdu.y));
                float2 ps01 = __half22float2(*reinterpret_cast<__half2*>(&psu.x));
                float2 ps23 = __half22float2(*reinterpret_cast<__half2*>(&psu.y));
                float a = __int_as_float(ed.z), dd = __int_as_float(ed.w);
                u.x = f2tf(silu_f(pd01.x + ps01.x + a * cw0.x + dd * cw1.x + cb1.x));
                u.y = f2tf(silu_f(pd01.y + ps01.y + a * cw0.y + dd * cw1.y + cb1.y));
                u.z = f2tf(silu_f(pd23.x + ps23.x + a * cw0.z + dd * cw1.z + cb1.z));
                u.w = f2tf(silu_f(pd23.y + ps23.y + a * cw0.w + dd * cw1.w + cb1.w));
            }
            *(uint4*)&HsU[e * E_LDA + k0] = u;
        }
        __syncthreads();

        // phase 2: [128x128] @ [128x32] tf32 MMA via ldmatrix
        float acc[2][4];
        #pragma unroll
        for (int ni = 0; ni < 2; ni++)
            #pragma unroll
            for (int q = 0; q < 4; q++) acc[ni][q] = 0.f;

        #pragma unroll 4
        for (int ks = 0; ks < 16; ++ks) {
            uint32_t a0, a1, a2, a3, b00, b10, b01, b11;
            ldsm_x4(a0, a1, a2, a3, aBase + ks * 32);
            ldsm_x4(b00, b10, b01, b11, bBase + ks * 32);
            mma_tf32(acc[0], a0, a1, a2, a3, b00, b01);
            mma_tf32(acc[1], a0, a1, a2, a3, b10, b11);
        }
        __syncthreads();

        {
            int r = mp * 16 + g;
            #pragma unroll
            for (int ni = 0; ni < 2; ni++) {
                int c = np * 16 + ni * 8 + 2 * tig;
                Ms[r * E_LDM + c]           = silu_f(acc[ni][0] + b2s[c]);
                Ms[r * E_LDM + c + 1]       = silu_f(acc[ni][1] + b2s[c + 1]);
                Ms[(r + 8) * E_LDM + c]     = silu_f(acc[ni][2] + b2s[c]);
                Ms[(r + 8) * E_LDM + c + 1] = silu_f(acc[ni][3] + b2s[c + 1]);
            }
        }
        __syncthreads();

        int e = tid >> 2;
        int cb = (tid & 3) * 8;
        int d = eds[e].y;
        if (d >= 0) {
            float4 v0 = *(const float4*)&Ms[e * E_LDM + cb];
            float4 v1 = *(const float4*)&Ms[e * E_LDM + cb + 4];
            atomicAdd((float4*)(g_mi + (d * MD + cb)), v0);
            atomicAdd((float4*)(g_mi + (d * MD + cb + 4)), v1);
        }
    }
}

// -------------------- LN stats --------------------
__global__ void stats_partial_kernel(const int* __restrict__ batch)
{
    __shared__ int s_lo, s_hi;
    __shared__ float rs[8], rs2[8];
    int g = blockIdx.x, part = blockIdx.y;
    int tid = threadIdx.x;
    if (tid == 0) { s_lo = lb_i(batch, NN, g); s_hi = lb_i(batch, NN, g + 1); }
    __syncthreads();
    int total = (s_hi - s_lo) * FP;
    int chunk = (total + 7) >> 3;
    int st = part * chunk;
    int en = st + chunk; if (en > total) en = total;
    const float* base = g_feats + (size_t)s_lo * FP;
    float s = 0.f, s2 = 0.f;
    for (int i = st + tid; i < en; i += 256) { float v = base[i]; s += v; s2 += v * v; }
    #pragma unroll
    for (int o = 16; o; o >>= 1) {
        s  += __shfl_down_sync(0xffffffffu, s, o);
        s2 += __shfl_down_sync(0xffffffffu, s2, o);
    }
    if ((tid & 31) == 0) { rs[tid >> 5] = s; rs2[tid >> 5] = s2; }
    __syncthreads();
    if (tid == 0) {
        float a = 0.f, b = 0.f;
        for (int i = 0; i < 8; i++) { a += rs[i]; b += rs2[i]; }
        atomicAdd(&g_sum[g], a); atomicAdd(&g_sum2[g], b);
    }
}

__global__ void stats_final_kernel(const int* __restrict__ batch)
{
    int g = threadIdx.x;
    if (g >= NG) return;
    int lo = lb_i(batch, NN, g), hi = lb_i(batch, NN, g + 1);
    int c = hi - lo; if (c < 1) c = 1;
    float denom = (float)c * 110.f;
    float mean = g_sum[g] / denom;
    float var = g_sum2[g] / denom - mean * mean;
    var = fmaxf(var, 0.f);
    g_mean[g] = mean;
    g_rstd[g] = rsqrtf(var + 1e-5f);
}

// ==================== persistent fused node MLP (512 thr, weights resident) ====================
#define NJ_LDA 148
#define NJ_LDB1 136
#define NJ_LDH 132
#define NJ_LDB2 136
#define NJ_TILES ((NN + 63) / 64)
#define NJ_GRID 296
#define NJ_SMEM ((64 * NJ_LDA + 144 * NJ_LDB1 + 64 * NJ_LDH + 128 * NJ_LDB2) * 4)
__global__ void __launch_bounds__(512) node_kernel(const int* __restrict__ batch,
    const float* __restrict__ nw1, const float* __restrict__ nb1,
    const float* __restrict__ nw2, const float* __restrict__ nb2,
    const float* __restrict__ lnw, const float* __restrict__ lnb, int l)
{
    extern __shared__ float sm[];
    uint32_t* Xs  = (uint32_t*)sm;
    uint32_t* W1s = Xs + 64 * NJ_LDA;
    uint32_t* Hs  = W1s + 144 * NJ_LDB1;
    uint32_t* W2s = Hs + 64 * NJ_LDH;
    int tid = threadIdx.x;

    const float* w1b = nw1 + (size_t)l * NIN * NH;
    for (int i = tid; i < 144 * NJ_LDB1; i += 512) {
        int k = i / NJ_LDB1, c = i % NJ_LDB1;
        W1s[i] = (k < NIN && c < NH) ? f2tf(w1b[(size_t)k * NH + c]) : 0u;
    }
    const float* w2b = nw2 + (size_t)l * NH * NF;
    for (int i = tid; i < 128 * NJ_LDB2; i += 512) {
        int k = i / NJ_LDB2, c = i % NJ_LDB2;
        W2s[i] = (c < NF) ? f2tf(w2b[(size_t)k * NF + c]) : 0u;
    }

    int w = tid >> 5, lane = tid & 31;
    int g = lane >> 2, tig = lane & 3;

    for (int tile = blockIdx.x; tile < NJ_TILES; tile += NJ_GRID) {
        int m0 = tile * 64;
        __syncthreads();
        for (int i = tid; i < 64 * NJ_LDA; i += 512) {
            int n = m0 + i / NJ_LDA, k = i % NJ_LDA;
            float v = 0.f;
            if (n < NN) {
                if (k < NF) {
                    int gg = batch[n];
                    float f = g_feats[(size_t)n * FP + k];
                    v = lnw[l * NF + k] * ((f - g_mean[gg]) * g_rstd[gg]) + lnb[l * NF + k];
                } else if (k < NIN) {
                    v = g_mi[(size_t)n * MD + (k - NF)];
                }
            }
            Xs[i] = f2tf(v);
        }
        __syncthreads();

        // ---- GEMM1: [64x144] @ [144x128]
        {
            int mp = w & 1, np = w >> 1;
            float acc[2][2][4];
            #pragma unroll
            for (int mi = 0; mi < 2; mi++)
                #pragma unroll
                for (int ni = 0; ni < 2; ni++)
                    #pragma unroll
                    for (int q = 0; q < 4; q++) acc[mi][ni][q] = 0.f;

            #pragma unroll 2
            for (int k0 = 0; k0 < 144; k0 += 8) {
                uint32_t a[2][4];
                #pragma unroll
                for (int mi = 0; mi < 2; mi++) {
                    int r0 = mp * 32 + mi * 16;
                    a[mi][0] = Xs[(r0 + g) * NJ_LDA + k0 + tig];
                    a[mi][1] = Xs[(r0 + g + 8) * NJ_LDA + k0 + tig];
                    a[mi][2] = Xs[(r0 + g) * NJ_LDA + k0 + tig + 4];
                    a[mi][3] = Xs[(r0 + g + 8) * NJ_LDA + k0 + tig + 4];
                }
                uint32_t b[2][2];
                #pragma unroll
                for (int ni = 0; ni < 2; ni++) {
                    int c0 = np * 16 + ni * 8 + g;
                    b[ni][0] = W1s[(k0 + tig) * NJ_LDB1 + c0];
                    b[ni][1] = W1s[(k0 + tig + 4) * NJ_LDB1 + c0];
                }
                #pragma unroll
                for (int mi = 0; mi < 2; mi++)
                    #pragma unroll
                    for (int ni = 0; ni < 2; ni++)
                        mma_tf32(acc[mi][ni], a[mi][0], a[mi][1], a[mi][2], a[mi][3], b[ni][0], b[ni][1]);
            }
            #pragma unroll
            for (int mi = 0; mi < 2; mi++) {
                int r = mp * 32 + mi * 16 + g;
                #pragma unroll
                for (int ni = 0; ni < 2; ni++) {
                    int cg = np * 16 + ni * 8 + 2 * tig;
                    float bb0 = nb1[l * NH + cg], bb1 = nb1[l * NH + cg + 1];
                    Hs[r * NJ_LDH + cg]           = f2tf(silu_f(acc[mi][ni][0] + bb0));
                    Hs[r * NJ_LDH + cg + 1]       = f2tf(silu_f(acc[mi][ni][1] + bb1));
                    Hs[(r + 8) * NJ_LDH + cg]     = f2tf(silu_f(acc[mi][ni][2] + bb0));
                    Hs[(r + 8) * NJ_LDH + cg + 1] = f2tf(silu_f(acc[mi][ni][3] + bb1));
                }
            }
        }
        __syncthreads();

        // ---- GEMM2: [64x128] @ [128x112]
        {
            int mp = w & 3, np = w >> 2;
            float acc[4][4];
            #pragma unroll
            for (int j = 0; j < 4; j++)
                #pragma unroll
                for (int q = 0; q < 4; q++) acc[j][q] = 0.f;

            #pragma unroll 2
            for (int k0 = 0; k0 < 128; k0 += 8) {
                uint32_t a0 = Hs[(mp * 16 + g) * NJ_LDH + k0 + tig];
                uint32_t a1 = Hs[(mp * 16 + g + 8) * NJ_LDH + k0 + tig];
                uint32_t a2 = Hs[(mp * 16 + g) * NJ_LDH + k0 + tig + 4];
                uint32_t a3 = Hs[(mp * 16 + g + 8) * NJ_LDH + k0 + tig + 4];
                uint32_t b[4][2];
                #pragma unroll
                for (int j = 0; j < 4; j++) {
                    int c0 = np * 32 + j * 8 + g;
                    b[j][0] = W2s[(k0 + tig) * NJ_LDB2 + c0];
                    b[j][1] = W2s[(k0 + tig + 4) * NJ_LDB2 + c0];
                }
                #pragma unroll
                for (int j = 0; j < 4; j++)
                    mma_tf32(acc[j], a0, a1, a2, a3, b[j][0], b[j][1]);
            }

            #pragma unroll
            for (int j = 0; j < 4; j++) {
                int c = np * 32 + j * 8 + 2 * tig;
                if (c >= NF) continue;
                float bb0 = nb2[l * NF + c], bb1 = nb2[l * NF + c + 1];
                int r = m0 + mp * 16 + g;
                if (r < NN) {
                    float2 f = *(float2*)&g_feats[(size_t)r * FP + c];
                    f.x += acc[j][0] + bb0; f.y += acc[j][1] + bb1;
                    *(float2*)&g_feats[(size_t)r * FP + c] = f;
                }
                if (r + 8 < NN) {
                    float2 f = *(float2*)&g_feats[(size_t)(r + 8) * FP + c];
                    f.x += acc[j][2] + bb0; f.y += acc[j][3] + bb1;
                    *(float2*)&g_feats[(size_t)(r + 8) * FP + c] = f;
                }
            }
        }

        for (int i = tid; i < 64 * MD; i += 512) {
            int n = m0 + i / MD;
            if (n < NN) g_mi[(size_t)n * MD + (i % MD)] = 0.f;
        }
    }
}

// -------------------- global mean pool --------------------
__global__ void pool_kernel(const int* __restrict__ batch, float* __restrict__ out)
{
    __shared__ int s_lo, s_hi;
    __shared__ float red[256];
    int g = blockIdx.x, tid = threadIdx.x;
    if (tid == 0) { s_lo = lb_i(batch, NN, g); s_hi = lb_i(batch, NN, g + 1); }
    __syncthreads();
    float s = 0.f;
    if (tid < 2 * FP) {
        int part = tid / FP;
        int k = tid % FP;
        for (int n = s_lo + part; n < s_hi; n += 2)
            s += g_feats[(size_t)n * FP + k];
    }
    red[tid] = s;
    __syncthreads();
    if (tid < NF) {
        int c = s_hi - s_lo; if (c < 1) c = 1;
        out[g * NF + tid] = (red[tid] + red[tid + FP]) / (float)c;
    }
}

// -------------------- launch --------------------
extern "C" void kernel_launch(void* const* d_in, const int* in_sizes, int n_in,
                              void* d_out, int out_size)
{
    const float* x     = (const float*)d_in[0];
    const int*   ei    = (const int*)  d_in[1];
    const float* eattr = (const float*)d_in[2];
    const float* pos   = (const float*)d_in[3];
    const int*   batch = (const int*)  d_in[4];
    const float* emb[10];
    for (int i = 0; i < 10; i++) emb[i] = (const float*)d_in[5 + i];
    const float* ew1 = (const float*)d_in[15];
    const float* eb1 = (const float*)d_in[16];
    const float* ew2 = (const float*)d_in[17];
    const float* eb2 = (const float*)d_in[18];
    const float* nw1 = (const float*)d_in[19];
    const float* nb1 = (const float*)d_in[20];
    const float* nw2 = (const float*)d_in[21];
    const float* nb2 = (const float*)d_in[22];
    const float* lnw = (const float*)d_in[23];
    const float* lnb = (const float*)d_in[24];
    float* out = (float*)d_out;

    cudaFuncSetAttribute(precompP_kernel, cudaFuncAttributeMaxDynamicSharedMemorySize, PP_SMEM);
    cudaFuncSetAttribute(edge_kernel,     cudaFuncAttributeMaxDynamicSharedMemorySize, EDGE_SMEM);
    cudaFuncSetAttribute(node_kernel,     cudaFuncAttributeMaxDynamicSharedMemorySize, NJ_SMEM);

    embed_kernel<<<(NN * FP + 255) / 256, 256>>>(x, emb[0], emb[1], emb[2], emb[3],
                                                 emb[4], emb[5], emb[6], emb[7], emb[8], emb[9]);
    ea_kernel<<<(NE + 255) / 256, 256>>>(ei, eattr, pos);

    for (int l = 0; l < 2; l++) {
        precompP_kernel<<<148, 512, PP_SMEM>>>(ew1, l);
        edge_kernel<<<E_GRID, 512, EDGE_SMEM>>>(ei, ew1, eb1, ew2, eb2, l);
        stats_partial_kernel<<<dim3(NG, 8), 256>>>(batch);
        stats_final_kernel<<<1, 64>>>(batch);
        node_kernel<<<NJ_GRID, 512, NJ_SMEM>>>(batch, nw1, nb1, nw2, nb2, lnw, lnb, l);
    }
    pool_kernel<<<NG, 256>>>(batch, out);
}

// round 11
// speedup vs baseline: 2.3184x; 1.1611x over previous
#include <cuda_runtime.h>
#include <cuda_fp16.h>
#include <math.h>
#include <stdint.h>

#define NN   50000
#define NE   800000
#define NEL  850000
#define NG   64
#define FP   112
#define NF   110
#define MD   32
#define EH   128
#define NH   128
#define NIN  142
#define EFD  222

// -------- device scratch --------
__device__ float  g_feats[NN * FP];
__device__ __half g_P[(size_t)NN * 256];      // fp16 (same mantissa as tf32)
__device__ float  g_mi[NN * MD];
__device__ float  g_ea[NE * 2];
__device__ float  g_sum[NG], g_sum2[NG];
__device__ float  g_mean[NG], g_rstd[NG];

// silu via HW tanh: x*sigmoid(x) = h*tanh(h) + h, h = x/2
__device__ __forceinline__ float silu_f(float x) {
    float h = 0.5f * x;
    float t;
    asm("tanh.approx.f32 %0, %1;" : "=f"(t) : "f"(h));
    return fmaf(h, t, h);
}
__device__ __forceinline__ uint32_t f2tf(float f) {
    uint32_t u; asm("cvt.rna.tf32.f32 %0, %1;" : "=r"(u) : "f"(f)); return u;
}
__device__ __forceinline__ void mma_tf32(float* d,
    uint32_t a0, uint32_t a1, uint32_t a2, uint32_t a3, uint32_t b0, uint32_t b1)
{
    asm volatile("mma.sync.aligned.m16n8k8.row.col.f32.tf32.tf32.f32 "
        "{%0,%1,%2,%3},{%4,%5,%6,%7},{%8,%9},{%0,%1,%2,%3};"
        : "+f"(d[0]), "+f"(d[1]), "+f"(d[2]), "+f"(d[3])
        : "r"(a0), "r"(a1), "r"(a2), "r"(a3), "r"(b0), "r"(b1));
}
__device__ __forceinline__ void mma_f16(float* d,
    uint32_t a0, uint32_t a1, uint32_t a2, uint32_t a3, uint32_t b0, uint32_t b1)
{
    asm volatile("mma.sync.aligned.m16n8k16.row.col.f32.f16.f16.f32 "
        "{%0,%1,%2,%3},{%4,%5,%6,%7},{%8,%9},{%0,%1,%2,%3};"
        : "+f"(d[0]), "+f"(d[1]), "+f"(d[2]), "+f"(d[3])
        : "r"(a0), "r"(a1), "r"(a2), "r"(a3), "r"(b0), "r"(b1));
}
__device__ __forceinline__ void ldsm_x4(uint32_t& r0, uint32_t& r1, uint32_t& r2, uint32_t& r3,
                                        uint32_t saddr)
{
    asm volatile("ldmatrix.sync.aligned.m8n8.x4.shared.b16 {%0,%1,%2,%3}, [%4];"
        : "=r"(r0), "=r"(r1), "=r"(r2), "=r"(r3) : "r"(saddr));
}
__device__ __forceinline__ int lb_i(const int* __restrict__ a, int n, int v) {
    int lo = 0, hi = n;
    while (lo < hi) { int m = (lo + hi) >> 1; if (a[m] < v) lo = m + 1; else hi = m; }
    return lo;
}

// -------------------- embed (+ zero g_mi) --------------------
__global__ void embed_kernel(const float* __restrict__ x,
    const float* __restrict__ e0, const float* __restrict__ e1,
    const float* __restrict__ e2, const float* __restrict__ e3,
    const float* __restrict__ e4, const float* __restrict__ e5,
    const float* __restrict__ e6, const float* __restrict__ e7,
    const float* __restrict__ e8, const float* __restrict__ e9)
{
    long idx = (long)blockIdx.x * blockDim.x + threadIdx.x;
    if (idx < (long)NN * MD) g_mi[idx] = 0.f;
    if (idx >= (long)NN * FP) return;
    int n = (int)(idx / FP), k = (int)(idx % FP);
    float v = 0.f;
    if (k < 6) {
        int keep = (k == 0) ? 0 : (10 + k);
        v = x[n * 16 + keep];
    } else if (k < 38) {
        int code = (int)x[n * 16 + 1];
        v = e0[code * 32 + (k - 6)];
    } else if (k < 110) {
        int t = (k - 38) >> 3, c = (k - 38) & 7;
        int code = (int)x[n * 16 + 2 + t];
        const float* es[9] = {e1, e2, e3, e4, e5, e6, e7, e8, e9};
        v = es[t][code * 8 + c];
    }
    g_feats[idx] = v;
}

// -------------------- edge attr + rel dist --------------------
__global__ void ea_kernel(const int* __restrict__ ei,
                          const float* __restrict__ eattr,
                          const float* __restrict__ pos)
{
    int e = blockIdx.x * blockDim.x + threadIdx.x;
    if (e >= NE) return;
    int s = ei[e], d = ei[NE + e];
    float dx = pos[s * 3 + 0] - pos[d * 3 + 0];
    float dy = pos[s * 3 + 1] - pos[d * 3 + 1];
    float dz = pos[s * 3 + 2] - pos[d * 3 + 2];
    g_ea[2 * e + 0] = eattr[e];
    g_ea[2 * e + 1] = dx * dx + dy * dy + dz * dz;
}

// ==================== persistent precompP (512 thr, both halves resident) ====================
#define PP_LDA 116
#define PP_LDB 264
#define PP_TILES ((NN + 63) / 64)
#define PP_SMEM ((64 * PP_LDA + 112 * PP_LDB) * 4)
__global__ void __launch_bounds__(512) precompP_kernel(const float* __restrict__ w1, int l)
{
    extern __shared__ float sm[];
    uint32_t* Xs = (uint32_t*)sm;              // 64 x 116
    uint32_t* Ws = Xs + 64 * PP_LDA;           // 112 x 264 (256 out-cols + pad)
    int tid = threadIdx.x;

    if (blockIdx.x == 0 && tid < 2 * NG) {
        if (tid < NG) g_sum[tid] = 0.f; else g_sum2[tid - NG] = 0.f;
    }

    const float* w1b = w1 + (size_t)l * EFD * EH;
    for (int i = tid; i < 112 * PP_LDB; i += 512) {
        int k = i / PP_LDB, c = i % PP_LDB;
        uint32_t v = 0u;
        if (k < 110 && c < 256) {
            const float* base = w1b + (c < 128 ? 0 : 110 * EH);
            v = f2tf(base[(size_t)k * EH + (c & 127)]);
        }
        Ws[i] = v;
    }

    int w = tid >> 5, lane = tid & 31;
    int g = lane >> 2, tig = lane & 3;
    int mp = w & 1;
    int ng = w >> 1;

    for (int tile = blockIdx.x; tile < PP_TILES; tile += 148) {
        int m0 = tile * 64;
        __syncthreads();
        // division-free X load: one row per warp per pass
        #pragma unroll
        for (int rr = 0; rr < 4; rr++) {
            int r = rr * 16 + w;
            int n = m0 + r;
            bool valid = n < NN;
            #pragma unroll
            for (int kk = 0; kk < 4; kk++) {
                int k = kk * 32 + lane;
                if (k < PP_LDA) {
                    float v = (valid && k < FP) ? g_feats[n * FP + k] : 0.f;
                    Xs[r * PP_LDA + k] = f2tf(v);
                }
            }
        }
        __syncthreads();

        float acc[2][4][4];
        #pragma unroll
        for (int mi = 0; mi < 2; mi++)
            #pragma unroll
            for (int j = 0; j < 4; j++)
                #pragma unroll
                for (int q = 0; q < 4; q++) acc[mi][j][q] = 0.f;

        #pragma unroll 2
        for (int k0 = 0; k0 < 112; k0 += 8) {
            uint32_t a[2][4];
            #pragma unroll
            for (int mi = 0; mi < 2; mi++) {
                int r0 = mp * 32 + mi * 16;
                a[mi][0] = Xs[(r0 + g) * PP_LDA + k0 + tig];
                a[mi][1] = Xs[(r0 + g + 8) * PP_LDA + k0 + tig];
                a[mi][2] = Xs[(r0 + g) * PP_LDA + k0 + tig + 4];
                a[mi][3] = Xs[(r0 + g + 8) * PP_LDA + k0 + tig + 4];
            }
            uint32_t b[4][2];
            #pragma unroll
            for (int j = 0; j < 4; j++) {
                int c0 = ng * 32 + j * 8 + g;
                b[j][0] = Ws[(k0 + tig) * PP_LDB + c0];
                b[j][1] = Ws[(k0 + tig + 4) * PP_LDB + c0];
            }
            #pragma unroll
            for (int mi = 0; mi < 2; mi++)
                #pragma unroll
                for (int j = 0; j < 4; j++)
                    mma_tf32(acc[mi][j], a[mi][0], a[mi][1], a[mi][2], a[mi][3], b[j][0], b[j][1]);
        }

        #pragma unroll
        for (int mi = 0; mi < 2; mi++) {
            int r = m0 + mp * 32 + mi * 16 + g;
            #pragma unroll
            for (int j = 0; j < 4; j++) {
                int col = ng * 32 + j * 8 + 2 * tig;
                if (r < NN)
                    *(__half2*)&g_P[(size_t)r * 256 + col] =
                        __float22half2_rn(make_float2(acc[mi][j][0], acc[mi][j][1]));
                if (r + 8 < NN)
                    *(__half2*)&g_P[(size_t)(r + 8) * 256 + col] =
                        __float22half2_rn(make_float2(acc[mi][j][2], acc[mi][j][3]));
            }
        }
    }
}

// ==================== persistent edge (512 thr): fp16 gather + fp16 MMA + scatter ====================
#define E_LDH 136       // pitch in halves for Hs2 / WT2
#define E_LDM 36
#define E_NT  ((NEL + 127) / 128)
#define E_GRID 296
// bytes: Hs2 128*136*2 | WT2 32*136*2 | b2s 32*4 | eds 128*16
#define EDGE_SMEM (128 * E_LDH * 2 + 32 * E_LDH * 2 + 32 * 4 + 128 * 16)
__global__ void __launch_bounds__(512, 2) edge_kernel(const int* __restrict__ ei,
    const float* __restrict__ w1, const float* __restrict__ b1,
    const float* __restrict__ w2, const float* __restrict__ b2, int l)
{
    extern __shared__ float sm[];
    __half* Hs2 = (__half*)sm;                    // 128 x 136 halves; reused as Ms (f32) later
    __half* WT2 = Hs2 + 128 * E_LDH;              // 32(c) x 136(k) transposed W2, fp16
    float*  b2s = (float*)(WT2 + 32 * E_LDH);
    int4*   eds = (int4*)(b2s + 32);
    float*  Ms  = sm;                             // 128 x 36 f32 (fits in Hs2 region)

    int tid = threadIdx.x;
    const float* w1b = w1 + (size_t)l * EFD * EH;

    int k0 = (tid & 31) * 4;                      // half-index within a 128-wide row
    float4 cw0 = *(const float4*)&w1b[220 * EH + k0];
    float4 cw1 = *(const float4*)&w1b[221 * EH + k0];
    float4 cb1 = *(const float4*)&b1[l * EH + k0];

    if (tid < 32) b2s[tid] = b2[l * MD + tid];
    for (int i = tid; i < 128 * 32; i += 512) {
        int k = i >> 5, c = i & 31;
        WT2[c * E_LDH + k] = __float2half_rn(w2[(size_t)l * EH * MD + i]);
    }

    int wid = tid >> 5, lane = tid & 31;
    int g = lane >> 2, tig = lane & 3;
    int mp = wid & 7;          // 16-row strip of edges
    int np = wid >> 3;         // 16-col strip

    // ldmatrix lane addressing (fp16, 4 8x8 matrices per x4)
    uint32_t HsS = (uint32_t)__cvta_generic_to_shared(Hs2);
    uint32_t WTS = (uint32_t)__cvta_generic_to_shared(WT2);
    int lm = lane >> 3;        // matrix id 0..3
    int lr = lane & 7;         // row within matrix
    // A frags: {m0,m1,m2,m3} = (rows+0,k0),(rows+8,k0),(rows+0,k8),(rows+8,k8)
    uint32_t aBase = HsS + (uint32_t)(((mp * 16 + (lm & 1) * 8 + lr) * E_LDH + (lm >> 1) * 8) * 2);
    // B frags: {m0,m1,m2,m3} = (n+0,k0),(n+0,k8),(n+8,k0),(n+8,k8)
    uint32_t bBase = WTS + (uint32_t)(((np * 16 + (lm >> 1) * 8 + lr) * E_LDH + (lm & 1) * 8) * 2);

    for (int tile = blockIdx.x; tile < E_NT; tile += E_GRID) {
        int e0 = tile * 128;
        __syncthreads();
        if (tid < 128) {
            int e = e0 + tid;
            int s = -1, d = -1; float a = 0.f, dd = 0.f;
            if (e < NEL) {
                if (e < NE) { s = ei[e]; d = ei[NE + e]; a = g_ea[2 * e]; dd = g_ea[2 * e + 1]; }
                else        { s = d = e - NE; }
            }
            eds[tid] = make_int4(s, d, __float_as_int(a), __float_as_int(dd));
        }
        __syncthreads();

        // phase 1: H = silu(Pd[dst] + Ps[src] + ea*w220 + dist*w221 + b1) -> fp16
        #pragma unroll
        for (int it = 0; it < 8; ++it) {
            int e = it * 16 + wid;
            int4 ed = eds[e];
            __half2 h01 = __float2half2_rn(0.f), h23 = h01;
            if (ed.y >= 0) {
                uint2 pdu = *(const uint2*)(g_P + (ed.y * 256 + k0));
                uint2 psu = *(const uint2*)(g_P + (ed.x * 256 + 128 + k0));
                float2 pd01 = __half22float2(*reinterpret_cast<__half2*>(&pdu.x));
                float2 pd23 = __half22float2(*reinterpret_cast<__half2*>(&pdu.y));
                float2 ps01 = __half22float2(*reinterpret_cast<__half2*>(&psu.x));
                float2 ps23 = __half22float2(*reinterpret_cast<__half2*>(&psu.y));
                float a = __int_as_float(ed.z), dd = __int_as_float(ed.w);
                float s0 = silu_f(pd01.x + ps01.x + a * cw0.x + dd * cw1.x + cb1.x);
                float s1 = silu_f(pd01.y + ps01.y + a * cw0.y + dd * cw1.y + cb1.y);
                float s2 = silu_f(pd23.x + ps23.x + a * cw0.z + dd * cw1.z + cb1.z);
                float s3 = silu_f(pd23.y + ps23.y + a * cw0.w + dd * cw1.w + cb1.w);
                h01 = __floats2half2_rn(s0, s1);
                h23 = __floats2half2_rn(s2, s3);
            }
            __half2* p = (__half2*)&Hs2[e * E_LDH + k0];
            p[0] = h01; p[1] = h23;
        }
        __syncthreads();

        // phase 2: [128x128] @ [128x32] fp16 MMA (k16), 8 k-steps
        float acc[2][4];
        #pragma unroll
        for (int ni = 0; ni < 2; ni++)
            #pragma unroll
            for (int q = 0; q < 4; q++) acc[ni][q] = 0.f;

        #pragma unroll 8
        for (int ks = 0; ks < 8; ++ks) {
            uint32_t a0, a1, a2, a3, b00, b01, b10, b11;
            ldsm_x4(a0, a1, a2, a3, aBase + ks * 32);
            ldsm_x4(b00, b01, b10, b11, bBase + ks * 32);
            mma_f16(acc[0], a0, a1, a2, a3, b00, b01);
            mma_f16(acc[1], a0, a1, a2, a3, b10, b11);
        }
        __syncthreads();   // done reading Hs2; reuse as Ms (f32)

        {
            int r = mp * 16 + g;
            #pragma unroll
            for (int ni = 0; ni < 2; ni++) {
                int c = np * 16 + ni * 8 + 2 * tig;
                Ms[r * E_LDM + c]           = silu_f(acc[ni][0] + b2s[c]);
                Ms[r * E_LDM + c + 1]       = silu_f(acc[ni][1] + b2s[c + 1]);
                Ms[(r + 8) * E_LDM + c]     = silu_f(acc[ni][2] + b2s[c]);
                Ms[(r + 8) * E_LDM + c + 1] = silu_f(acc[ni][3] + b2s[c + 1]);
            }
        }
        __syncthreads();

        // scatter: 4 threads per edge, 2 float4 RED each
        int e = tid >> 2;
        int cb = (tid & 3) * 8;
        int d = eds[e].y;
        if (d >= 0) {
            float4 v0 = *(const float4*)&Ms[e * E_LDM + cb];
            float4 v1 = *(const float4*)&Ms[e * E_LDM + cb + 4];
            atomicAdd((float4*)(g_mi + (d * MD + cb)), v0);
            atomicAdd((float4*)(g_mi + (d * MD + cb + 4)), v1);
        }
    }
}

// -------------------- LN stats --------------------
__global__ void stats_partial_kernel(const int* __restrict__ batch)
{
    __shared__ int s_lo, s_hi;
    __shared__ float rs[8], rs2[8];
    int g = blockIdx.x, part = blockIdx.y;
    int tid = threadIdx.x;
    if (tid == 0) { s_lo = lb_i(batch, NN, g); s_hi = lb_i(batch, NN, g + 1); }
    __syncthreads();
    int total = (s_hi - s_lo) * FP;
    int chunk = (total + 7) >> 3;
    int st = part * chunk;
    int en = st + chunk; if (en > total) en = total;
    const float* base = g_feats + (size_t)s_lo * FP;
    float s = 0.f, s2 = 0.f;
    for (int i = st + tid; i < en; i += 256) { float v = base[i]; s += v; s2 += v * v; }
    #pragma unroll
    for (int o = 16; o; o >>= 1) {
        s  += __shfl_down_sync(0xffffffffu, s, o);
        s2 += __shfl_down_sync(0xffffffffu, s2, o);
    }
    if ((tid & 31) == 0) { rs[tid >> 5] = s; rs2[tid >> 5] = s2; }
    __syncthreads();
    if (tid == 0) {
        float a = 0.f, b = 0.f;
        for (int i = 0; i < 8; i++) { a += rs[i]; b += rs2[i]; }
        atomicAdd(&g_sum[g], a); atomicAdd(&g_sum2[g], b);
    }
}

__global__ void stats_final_kernel(const int* __restrict__ batch)
{
    int g = threadIdx.x;
    if (g >= NG) return;
    int lo = lb_i(batch, NN, g), hi = lb_i(batch, NN, g + 1);
    int c = hi - lo; if (c < 1) c = 1;
    float denom = (float)c * 110.f;
    float mean = g_sum[g] / denom;
    float var = g_sum2[g] / denom - mean * mean;
    var = fmaxf(var, 0.f);
    g_mean[g] = mean;
    g_rstd[g] = rsqrtf(var + 1e-5f);
}

// ==================== persistent fused node MLP (512 thr, weights + vectors resident) ====================
#define NJ_LDA 148
#define NJ_LDB1 136
#define NJ_LDH 132
#define NJ_LDB2 136
#define NJ_TILES ((NN + 63) / 64)
#define NJ_GRID 296
#define NJ_VEC (128 + 112 + 110 + 110)   // nb1 | nb2 | lnw | lnb
#define NJ_SMEM ((64 * NJ_LDA + 144 * NJ_LDB1 + 64 * NJ_LDH + 128 * NJ_LDB2 + NJ_VEC) * 4)
__global__ void __launch_bounds__(512) node_kernel(const int* __restrict__ batch,
    const float* __restrict__ nw1, const float* __restrict__ nb1,
    const float* __restrict__ nw2, const float* __restrict__ nb2,
    const float* __restrict__ lnw, const float* __restrict__ lnb, int l)
{
    extern __shared__ float sm[];
    uint32_t* Xs   = (uint32_t*)sm;
    uint32_t* W1s  = Xs + 64 * NJ_LDA;
    uint32_t* Hs   = W1s + 144 * NJ_LDB1;
    uint32_t* W2s  = Hs + 64 * NJ_LDH;
    float*    nb1s = (float*)(W2s + 128 * NJ_LDB2);
    float*    nb2s = nb1s + 128;
    float*    lnws = nb2s + 112;
    float*    lnbs = lnws + 110;
    int tid = threadIdx.x;

    const float* w1b = nw1 + (size_t)l * NIN * NH;
    for (int i = tid; i < 144 * NJ_LDB1; i += 512) {
        int k = i / NJ_LDB1, c = i % NJ_LDB1;
        W1s[i] = (k < NIN && c < NH) ? f2tf(w1b[(size_t)k * NH + c]) : 0u;
    }
    const float* w2b = nw2 + (size_t)l * NH * NF;
    for (int i = tid; i < 128 * NJ_LDB2; i += 512) {
        int k = i / NJ_LDB2, c = i % NJ_LDB2;
        W2s[i] = (c < NF) ? f2tf(w2b[(size_t)k * NF + c]) : 0u;
    }
    if (tid < 128) nb1s[tid] = nb1[l * NH + tid];
    if (tid >= 128 && tid < 240) {
        int c = tid - 128;
        nb2s[c] = (c < NF) ? nb2[l * NF + c] : 0.f;
    }
    if (tid >= 256 && tid < 366) {
        int c = tid - 256;
        lnws[c] = lnw[l * NF + c];
        lnbs[c] = lnb[l * NF + c];
    }

    int w = tid >> 5, lane = tid & 31;
    int g = lane >> 2, tig = lane & 3;

    for (int tile = blockIdx.x; tile < NJ_TILES; tile += NJ_GRID) {
        int m0 = tile * 64;
        __syncthreads();
        // division-free X load: one row per warp per pass (batch/mean/rstd once per row)
        #pragma unroll
        for (int rr = 0; rr < 4; rr++) {
            int r = rr * 16 + w;
            int n = m0 + r;
            bool valid = n < NN;
            float mean = 0.f, rstd = 0.f;
            if (valid) { int gg = batch[n]; mean = g_mean[gg]; rstd = g_rstd[gg]; }
            #pragma unroll
            for (int kk = 0; kk < 5; kk++) {
                int k = kk * 32 + lane;
                if (k < NJ_LDA) {
                    float v = 0.f;
                    if (valid) {
                        if (k < NF)
                            v = lnws[k] * ((g_feats[n * FP + k] - mean) * rstd) + lnbs[k];
                        else if (k < NIN)
                            v = g_mi[n * MD + (k - NF)];
                    }
                    Xs[r * NJ_LDA + k] = f2tf(v);
                }
            }
        }
        __syncthreads();

        // ---- GEMM1: [64x144] @ [144x128]
        {
            int mp = w & 1, np = w >> 1;
            float acc[2][2][4];
            #pragma unroll
            for (int mi = 0; mi < 2; mi++)
                #pragma unroll
                for (int ni = 0; ni < 2; ni++)
                    #pragma unroll
                    for (int q = 0; q < 4; q++) acc[mi][ni][q] = 0.f;

            #pragma unroll 2
            for (int k0 = 0; k0 < 144; k0 += 8) {
                uint32_t a[2][4];
                #pragma unroll
                for (int mi = 0; mi < 2; mi++) {
                    int r0 = mp * 32 + mi * 16;
                    a[mi][0] = Xs[(r0 + g) * NJ_LDA + k0 + tig];
                    a[mi][1] = Xs[(r0 + g + 8) * NJ_LDA + k0 + tig];
                    a[mi][2] = Xs[(r0 + g) * NJ_LDA + k0 + tig + 4];
                    a[mi][3] = Xs[(r0 + g + 8) * NJ_LDA + k0 + tig + 4];
                }
                uint32_t b[2][2];
                #pragma unroll
                for (int ni = 0; ni < 2; ni++) {
                    int c0 = np * 16 + ni * 8 + g;
                    b[ni][0] = W1s[(k0 + tig) * NJ_LDB1 + c0];
                    b[ni][1] = W1s[(k0 + tig + 4) * NJ_LDB1 + c0];
                }
                #pragma unroll
                for (int mi = 0; mi < 2; mi++)
                    #pragma unroll
                    for (int ni = 0; ni < 2; ni++)
                        mma_tf32(acc[mi][ni], a[mi][0], a[mi][1], a[mi][2], a[mi][3], b[ni][0], b[ni][1]);
            }
            #pragma unroll
            for (int mi = 0; mi < 2; mi++) {
                int r = mp * 32 + mi * 16 + g;
                #pragma unroll
                for (int ni = 0; ni < 2; ni++) {
                    int cg = np * 16 + ni * 8 + 2 * tig;
                    float bb0 = nb1s[cg], bb1 = nb1s[cg + 1];
                    Hs[r * NJ_LDH + cg]           = f2tf(silu_f(acc[mi][ni][0] + bb0));
                    Hs[r * NJ_LDH + cg + 1]       = f2tf(silu_f(acc[mi][ni][1] + bb1));
                    Hs[(r + 8) * NJ_LDH + cg]     = f2tf(silu_f(acc[mi][ni][2] + bb0));
                    Hs[(r + 8) * NJ_LDH + cg + 1] = f2tf(silu_f(acc[mi][ni][3] + bb1));
                }
            }
        }
        __syncthreads();

        // ---- GEMM2: [64x128] @ [128x112]
        {
            int mp = w & 3, np = w >> 2;
            float acc[4][4];
            #pragma unroll
            for (int j = 0; j < 4; j++)
                #pragma unroll
                for (int q = 0; q < 4; q++) acc[j][q] = 0.f;

            #pragma unroll 2
            for (int k0 = 0; k0 < 128; k0 += 8) {
                uint32_t a0 = Hs[(mp * 16 + g) * NJ_LDH + k0 + tig];
                uint32_t a1 = Hs[(mp * 16 + g + 8) * NJ_LDH + k0 + tig];
                uint32_t a2 = Hs[(mp * 16 + g) * NJ_LDH + k0 + tig + 4];
                uint32_t a3 = Hs[(mp * 16 + g + 8) * NJ_LDH + k0 + tig + 4];
                uint32_t b[4][2];
                #pragma unroll
                for (int j = 0; j < 4; j++) {
                    int c0 = np * 32 + j * 8 + g;
                    b[j][0] = W2s[(k0 + tig) * NJ_LDB2 + c0];
                    b[j][1] = W2s[(k0 + tig + 4) * NJ_LDB2 + c0];
                }
                #pragma unroll
                for (int j = 0; j < 4; j++)
                    mma_tf32(acc[j], a0, a1, a2, a3, b[j][0], b[j][1]);
            }

            #pragma unroll
            for (int j = 0; j < 4; j++) {
                int c = np * 32 + j * 8 + 2 * tig;
                if (c >= NF) continue;
                float bb0 = nb2s[c], bb1 = nb2s[c + 1];
                int r = m0 + mp * 16 + g;
                if (r < NN) {
                    float2 f = *(float2*)&g_feats[(size_t)r * FP + c];
                    f.x += acc[j][0] + bb0; f.y += acc[j][1] + bb1;
                    *(float2*)&g_feats[(size_t)r * FP + c] = f;
                }
                if (r + 8 < NN) {
                    float2 f = *(float2*)&g_feats[(size_t)(r + 8) * FP + c];
                    f.x += acc[j][2] + bb0; f.y += acc[j][3] + bb1;
                    *(float2*)&g_feats[(size_t)(r + 8) * FP + c] = f;
                }
            }
        }

        for (int i = tid; i < 64 * MD; i += 512) {
            int n = m0 + i / MD;
            if (n < NN) g_mi[(size_t)n * MD + (i % MD)] = 0.f;
        }
    }
}

// -------------------- global mean pool --------------------
__global__ void pool_kernel(const int* __restrict__ batch, float* __restrict__ out)
{
    __shared__ int s_lo, s_hi;
    __shared__ float red[256];
    int g = blockIdx.x, tid = threadIdx.x;
    if (tid == 0) { s_lo = lb_i(batch, NN, g); s_hi = lb_i(batch, NN, g + 1); }
    __syncthreads();
    float s = 0.f;
    if (tid < 2 * FP) {
        int part = tid / FP;
        int k = tid % FP;
        for (int n = s_lo + part; n < s_hi; n += 2)
            s += g_feats[(size_t)n * FP + k];
    }
    red[tid] = s;
    __syncthreads();
    if (tid < NF) {
        int c = s_hi - s_lo; if (c < 1) c = 1;
        out[g * NF + tid] = (red[tid] + red[tid + FP]) / (float)c;
    }
}

// -------------------- launch --------------------
extern "C" void kernel_launch(void* const* d_in, const int* in_sizes, int n_in,
                              void* d_out, int out_size)
{
    const float* x     = (const float*)d_in[0];
    const int*   ei    = (const int*)  d_in[1];
    const float* eattr = (const float*)d_in[2];
    const float* pos   = (const float*)d_in[3];
    const int*   batch = (const int*)  d_in[4];
    const float* emb[10];
    for (int i = 0; i < 10; i++) emb[i] = (const float*)d_in[5 + i];
    const float* ew1 = (const float*)d_in[15];
    const float* eb1 = (const float*)d_in[16];
    const float* ew2 = (const float*)d_in[17];
    const float* eb2 = (const float*)d_in[18];
    const float* nw1 = (const float*)d_in[19];
    const float* nb1 = (const float*)d_in[20];
    const float* nw2 = (const float*)d_in[21];
    const float* nb2 = (const float*)d_in[22];
    const float* lnw = (const float*)d_in[23];
    const float* lnb = (const float*)d_in[24];
    float* out = (float*)d_out;

    cudaFuncSetAttribute(precompP_kernel, cudaFuncAttributeMaxDynamicSharedMemorySize, PP_SMEM);
    cudaFuncSetAttribute(edge_kernel,     cudaFuncAttributeMaxDynamicSharedMemorySize, EDGE_SMEM);
    cudaFuncSetAttribute(node_kernel,     cudaFuncAttributeMaxDynamicSharedMemorySize, NJ_SMEM);

    embed_kernel<<<(NN * FP + 255) / 256, 256>>>(x, emb[0], emb[1], emb[2], emb[3],
                                                 emb[4], emb[5], emb[6], emb[7], emb[8], emb[9]);
    ea_kernel<<<(NE + 255) / 256, 256>>>(ei, eattr, pos);

    for (int l = 0; l < 2; l++) {
        precompP_kernel<<<148, 512, PP_SMEM>>>(ew1, l);
        edge_kernel<<<E_GRID, 512, EDGE_SMEM>>>(ei, ew1, eb1, ew2, eb2, l);
        stats_partial_kernel<<<dim3(NG, 8), 256>>>(batch);
        stats_final_kernel<<<1, 64>>>(batch);
        node_kernel<<<NJ_GRID, 512, NJ_SMEM>>>(batch, nw1, nb1, nw2, nb2, lnw, lnb, l);
    }
    pool_kernel<<<NG, 256>>>(batch, out);
}